// round 1
// baseline (speedup 1.0000x reference)
#include <cuda_runtime.h>
#include <math.h>

#define HEADS   8
#define DH      64
#define NSEQ    2048
#define BATCH   4
#define DMODEL  512
#define ROWS    (BATCH*NSEQ)    // 8192
#define BHN     (BATCH*HEADS)   // 32
#define QT      16
#define KT      256

// ---------------- scratch (device globals; no allocations) ----------------
__device__ float g_Q[BHN*NSEQ*DH];
__device__ float g_K[BHN*NSEQ*DH];
__device__ float g_V[BHN*NSEQ*DH];
__device__ float g_O[(size_t)ROWS*DMODEL];
__device__ float g_Y[(size_t)ROWS*DMODEL];

// ---------------- generic K=512 SGEMM, 128x128 tile, 8x8 microtile --------
// MODE 0: A = X (param), B = w_qkv (ldb=1536), epilogue scatters into g_Q/g_K/g_V [b,h,n,dh]
// MODE 1: A = g_O,       B = w_unify (ldb=512), epilogue adds bias, writes g_Y
template<int MODE>
__global__ void __launch_bounds__(256)
gemm_k512(const float* __restrict__ A_in, const float* __restrict__ B,
          const float* __restrict__ bias, int ldb)
{
    __shared__ float As[8][128];
    __shared__ float Bs[8][128];
    const float* A = (MODE == 0) ? A_in : g_O;

    const int bm = blockIdx.y * 128;
    const int bn = blockIdx.x * 128;
    const int tid = threadIdx.x;
    const int ty = tid >> 4, tx = tid & 15;
    const int lrow = tid >> 1, lseg = (tid & 1) << 2;   // A-tile load
    const int brow = tid >> 5, bcol = (tid & 31) << 2;  // B-tile load

    float acc[8][8];
    #pragma unroll
    for (int i = 0; i < 8; i++)
        #pragma unroll
        for (int j = 0; j < 8; j++) acc[i][j] = 0.f;

    for (int k0 = 0; k0 < 512; k0 += 8) {
        float4 av = *(const float4*)(A + (size_t)(bm + lrow)*512 + k0 + lseg);
        float4 bv = *(const float4*)(B + (size_t)(k0 + brow)*ldb + bn + bcol);
        As[lseg+0][lrow] = av.x; As[lseg+1][lrow] = av.y;
        As[lseg+2][lrow] = av.z; As[lseg+3][lrow] = av.w;
        *(float4*)&Bs[brow][bcol] = bv;
        __syncthreads();
        #pragma unroll
        for (int k = 0; k < 8; k++) {
            float a[8], b[8];
            *(float4*)(a)   = *(const float4*)&As[k][ty*8];
            *(float4*)(a+4) = *(const float4*)&As[k][ty*8+4];
            *(float4*)(b)   = *(const float4*)&Bs[k][tx*8];
            *(float4*)(b+4) = *(const float4*)&Bs[k][tx*8+4];
            #pragma unroll
            for (int i = 0; i < 8; i++)
                #pragma unroll
                for (int j = 0; j < 8; j++) acc[i][j] += a[i]*b[j];
        }
        __syncthreads();
    }

    if (MODE == 0) {
        const int which = bn >> 9;            // 0:q 1:k 2:v (tile never straddles)
        float* dst = (which == 0) ? g_Q : (which == 1) ? g_K : g_V;
        const int cbase = bn - (which << 9);
        #pragma unroll
        for (int i = 0; i < 8; i++) {
            const int r = bm + ty*8 + i;
            const int bidx = r >> 11, nidx = r & (NSEQ-1);
            #pragma unroll
            for (int j = 0; j < 8; j++) {
                const int c = cbase + tx*8 + j;
                const int h = c >> 6, dd = c & 63;
                dst[(((size_t)bidx*HEADS + h)*NSEQ + nidx)*DH + dd] = acc[i][j];
            }
        }
    } else {
        float bz[8];
        *(float4*)(bz)   = *(const float4*)(bias + bn + tx*8);
        *(float4*)(bz+4) = *(const float4*)(bias + bn + tx*8 + 4);
        #pragma unroll
        for (int i = 0; i < 8; i++) {
            const int r = bm + ty*8 + i;
            float* yr = &g_Y[(size_t)r*DMODEL + bn + tx*8];
            *(float4*)(yr)   = make_float4(acc[i][0]+bz[0], acc[i][1]+bz[1],
                                           acc[i][2]+bz[2], acc[i][3]+bz[3]);
            *(float4*)(yr+4) = make_float4(acc[i][4]+bz[4], acc[i][5]+bz[5],
                                           acc[i][6]+bz[6], acc[i][7]+bz[7]);
        }
    }
}

// ---------------- fused attention: scores+bias -> softmax -> attn out + PV --
// One block = (bh, 16-query tile). Whole 16x2048 score row held in smem.
#define ATTN_SMEM ((QT*NSEQ + KT*DH + DH*QT + KT + QT) * 4)

__global__ void __launch_bounds__(256)
attn_kernel(float* __restrict__ attn_out)
{
    extern __shared__ float sm[];
    float* S    = sm;                   // [QT][NSEQ]      131072 B
    float* KV   = S   + QT*NSEQ;        // K^T [DH][KT] / V [KT][DH]  65536 B
    float* Qst  = KV  + KT*DH;          // Q^T [DH][QT]    4096 B
    float* sdec = Qst + DH*QT;          // (unused slot, kept for alignment)
    float* rowl = sdec + KT;            // [QT] reciprocal row sums

    const int tid = threadIdx.x;
    const int bh  = blockIdx.y;
    const int q0  = blockIdx.x * QT;
    const float* Qb = g_Q + (size_t)bh*NSEQ*DH;
    const float* Kb = g_K + (size_t)bh*NSEQ*DH;
    const float* Vb = g_V + (size_t)bh*NSEQ*DH;
    const float scale = 0.125f;         // 1/sqrt(64)

    // Q tile transposed: Qst[d][i]
    for (int idx = tid; idx < QT*DH; idx += 256) {
        int i = idx & (QT-1), d = idx >> 4;
        Qst[d*QT + i] = Qb[(size_t)(q0+i)*DH + d];
    }

    // ---- phase 1: S[i][k] = scale*q.k + exp(-k/50) ----
    const int ty = tid >> 6;    // 4 row-groups (4 rows each)
    const int tx = tid & 63;    // 64 col-groups (4 keys each)
    for (int kt = 0; kt < NSEQ/KT; ++kt) {
        __syncthreads();
        // K tile transposed: KV[d][k]
        const float* Krow = Kb + (size_t)(kt*KT + tid)*DH;
        #pragma unroll
        for (int d4 = 0; d4 < DH; d4 += 4) {
            float4 v = *(const float4*)(Krow + d4);
            KV[(d4+0)*KT + tid] = v.x;
            KV[(d4+1)*KT + tid] = v.y;
            KV[(d4+2)*KT + tid] = v.z;
            KV[(d4+3)*KT + tid] = v.w;
        }
        __syncthreads();
        float acc[4][4];
        #pragma unroll
        for (int i = 0; i < 4; i++)
            #pragma unroll
            for (int j = 0; j < 4; j++) acc[i][j] = 0.f;
        #pragma unroll 8
        for (int d = 0; d < DH; ++d) {
            float a[4], b[4];
            *(float4*)a = *(const float4*)(Qst + d*QT + ty*4);   // broadcast
            *(float4*)b = *(const float4*)(KV  + d*KT + tx*4);   // conflict-free
            #pragma unroll
            for (int i = 0; i < 4; i++)
                #pragma unroll
                for (int j = 0; j < 4; j++) acc[i][j] += a[i]*b[j];
        }
        float dec[4];
        #pragma unroll
        for (int j = 0; j < 4; j++)
            dec[j] = __expf(-(float)(kt*KT + tx*4 + j) * (1.0f/50.0f));
        #pragma unroll
        for (int i = 0; i < 4; i++) {
            float4 st = make_float4(acc[i][0]*scale + dec[0],
                                    acc[i][1]*scale + dec[1],
                                    acc[i][2]*scale + dec[2],
                                    acc[i][3]*scale + dec[3]);
            *(float4*)(S + (size_t)(ty*4+i)*NSEQ + kt*KT + tx*4) = st;
        }
    }
    __syncthreads();

    // ---- phase 2: softmax per row (warp w handles rows 2w, 2w+1) ----
    const int w = tid >> 5, lane = tid & 31;
    #pragma unroll
    for (int rr = 0; rr < 2; ++rr) {
        const int r = w*2 + rr;
        float* Srow = S + (size_t)r*NSEQ;
        float m = -1e30f;
        for (int k = lane; k < NSEQ; k += 32) m = fmaxf(m, Srow[k]);
        #pragma unroll
        for (int off = 16; off; off >>= 1)
            m = fmaxf(m, __shfl_xor_sync(0xffffffffu, m, off));
        float l = 0.f;
        for (int k = lane*4; k < NSEQ; k += 128) {
            float4 p = *(float4*)(Srow + k);
            p.x = __expf(p.x - m); p.y = __expf(p.y - m);
            p.z = __expf(p.z - m); p.w = __expf(p.w - m);
            l += p.x + p.y + p.z + p.w;
            *(float4*)(Srow + k) = p;
        }
        #pragma unroll
        for (int off = 16; off; off >>= 1)
            l += __shfl_xor_sync(0xffffffffu, l, off);
        if (lane == 0) rowl[r] = 1.0f / l;
    }
    __syncthreads();

    // ---- phase 3: normalize, write attn output ----
    float* aout = attn_out + ((size_t)bh*NSEQ + q0)*NSEQ;
    for (int idx = tid; idx < QT*NSEQ/4; idx += 256) {
        const int r = idx >> 9;              // NSEQ/4 = 512 float4 per row
        const float inv = rowl[r];
        float4 p = *(float4*)(S + (size_t)idx*4);
        p.x *= inv; p.y *= inv; p.z *= inv; p.w *= inv;
        *(float4*)(S + (size_t)idx*4) = p;
        *(float4*)(aout + (size_t)idx*4) = p;
    }

    // ---- phase 4: O = P @ V ----
    const int row = tid >> 4;              // 16 rows
    const int dc  = (tid & 15) << 2;       // d quad
    float o0=0.f, o1=0.f, o2=0.f, o3=0.f;
    for (int kt = 0; kt < NSEQ/KT; ++kt) {
        __syncthreads();
        const float* Vt = Vb + (size_t)kt*KT*DH;
        for (int t4 = tid; t4 < KT*DH/4; t4 += 256)
            *(float4*)(KV + (size_t)t4*4) = *(const float4*)(Vt + (size_t)t4*4);
        __syncthreads();
        const float* Srow = S + (size_t)row*NSEQ + kt*KT;
        #pragma unroll 8
        for (int k = 0; k < KT; ++k) {
            const float p = Srow[k];
            float4 v = *(const float4*)(KV + k*DH + dc);
            o0 += p*v.x; o1 += p*v.y; o2 += p*v.z; o3 += p*v.w;
        }
    }
    const int b = bh >> 3, h = bh & 7;
    *(float4*)&g_O[((size_t)(b*NSEQ + q0 + row))*DMODEL + h*DH + dc] =
        make_float4(o0, o1, o2, o3);
}

// ---------------- LayerNorm over 512 cols, one block per row --------------
__global__ void __launch_bounds__(256)
ln_kernel(const float* __restrict__ gamma, const float* __restrict__ beta,
          float* __restrict__ out)
{
    const int r = blockIdx.x, tid = threadIdx.x;
    const float* y = g_Y + (size_t)r*DMODEL;
    const float a = y[tid], b = y[tid + 256];
    float s  = a + b;
    float sq = a*a + b*b;
    #pragma unroll
    for (int off = 16; off; off >>= 1) {
        s  += __shfl_xor_sync(0xffffffffu, s,  off);
        sq += __shfl_xor_sync(0xffffffffu, sq, off);
    }
    __shared__ float ws[8], wq[8];
    __shared__ float mean_s, inv_s;
    if ((tid & 31) == 0) { ws[tid >> 5] = s; wq[tid >> 5] = sq; }
    __syncthreads();
    if (tid == 0) {
        float S = 0.f, Q = 0.f;
        #pragma unroll
        for (int i = 0; i < 8; i++) { S += ws[i]; Q += wq[i]; }
        const float mean = S * (1.0f/512.0f);
        const float var  = Q * (1.0f/512.0f) - mean*mean;
        mean_s = mean;
        inv_s  = rsqrtf(var + 1e-5f);
    }
    __syncthreads();
    out[(size_t)r*DMODEL + tid]       = (a - mean_s)*inv_s*gamma[tid]       + beta[tid];
    out[(size_t)r*DMODEL + tid + 256] = (b - mean_s)*inv_s*gamma[tid + 256] + beta[tid + 256];
}

// ---------------- launch ---------------------------------------------------
extern "C" void kernel_launch(void* const* d_in, const int* in_sizes, int n_in,
                              void* d_out, int out_size)
{
    const float* x        = (const float*)d_in[0];
    const float* w_qkv    = (const float*)d_in[1];
    const float* w_unify  = (const float*)d_in[2];
    const float* b_unify  = (const float*)d_in[3];
    const float* ln_gamma = (const float*)d_in[4];
    const float* ln_beta  = (const float*)d_in[5];

    float* out_ln   = (float*)d_out;
    float* out_attn = out_ln + (size_t)ROWS*DMODEL;   // ln first, attn second

    cudaFuncSetAttribute(attn_kernel,
                         cudaFuncAttributeMaxDynamicSharedMemorySize, ATTN_SMEM);

    // 1) QKV projection into [b,h,n,dh] scratch
    gemm_k512<0><<<dim3(12, 64), 256>>>(x, w_qkv, nullptr, 3*DMODEL);
    // 2) fused attention (scores + decay bias + softmax + attn write + PV)
    attn_kernel<<<dim3(NSEQ/QT, BHN), 256, ATTN_SMEM>>>(out_attn);
    // 3) unify GEMM + bias
    gemm_k512<1><<<dim3(4, 64), 256>>>(nullptr, w_unify, b_unify, DMODEL);
    // 4) LayerNorm -> first output
    ln_kernel<<<ROWS, 256>>>(ln_gamma, ln_beta, out_ln);
}

// round 2
// speedup vs baseline: 2.3053x; 2.3053x over previous
#include <cuda_runtime.h>
#include <math.h>

#define HEADS   8
#define DH      64
#define NSEQ    2048
#define BATCH   4
#define DMODEL  512
#define ROWS    (BATCH*NSEQ)    // 8192
#define BHN     (BATCH*HEADS)   // 32

// ---------------- scratch (device globals; no allocations) ----------------
__device__ float g_Q[(size_t)BHN*NSEQ*DH];     // [bh][n][dh]
__device__ float g_K[(size_t)BHN*NSEQ*DH];     // [bh][n][dh]
__device__ float g_V[(size_t)BHN*NSEQ*DH];     // [bh][n][dh]
__device__ float g_O[(size_t)ROWS*DMODEL];
__device__ float g_Y[(size_t)ROWS*DMODEL];
__device__ float g_part[(size_t)BHN*16*NSEQ];  // [bh][ktile][q] partial exp-sums

// ---------------- generic K=512 SGEMM, 128x128 tile, 8x8 microtile --------
// MODE 0: A = X, B = w_qkv (ldb=1536), scatters into g_Q/g_K/g_V [bh][n][dh]
// MODE 1: A = g_O, B = w_unify (ldb=512), adds bias, writes g_Y
template<int MODE>
__global__ void __launch_bounds__(256)
gemm_k512(const float* __restrict__ A_in, const float* __restrict__ B,
          const float* __restrict__ bias, int ldb)
{
    __shared__ float As[8][128];
    __shared__ float Bs[8][128];
    const float* A = (MODE == 0) ? A_in : g_O;

    const int bm = blockIdx.y * 128;
    const int bn = blockIdx.x * 128;
    const int tid = threadIdx.x;
    const int ty = tid >> 4, tx = tid & 15;
    const int lrow = tid >> 1, lseg = (tid & 1) << 2;
    const int brow = tid >> 5, bcol = (tid & 31) << 2;

    float acc[8][8];
    #pragma unroll
    for (int i = 0; i < 8; i++)
        #pragma unroll
        for (int j = 0; j < 8; j++) acc[i][j] = 0.f;

    for (int k0 = 0; k0 < 512; k0 += 8) {
        float4 av = *(const float4*)(A + (size_t)(bm + lrow)*512 + k0 + lseg);
        float4 bv = *(const float4*)(B + (size_t)(k0 + brow)*ldb + bn + bcol);
        As[lseg+0][lrow] = av.x; As[lseg+1][lrow] = av.y;
        As[lseg+2][lrow] = av.z; As[lseg+3][lrow] = av.w;
        *(float4*)&Bs[brow][bcol] = bv;
        __syncthreads();
        #pragma unroll
        for (int k = 0; k < 8; k++) {
            float a[8], b[8];
            *(float4*)(a)   = *(const float4*)&As[k][ty*8];
            *(float4*)(a+4) = *(const float4*)&As[k][ty*8+4];
            *(float4*)(b)   = *(const float4*)&Bs[k][tx*8];
            *(float4*)(b+4) = *(const float4*)&Bs[k][tx*8+4];
            #pragma unroll
            for (int i = 0; i < 8; i++)
                #pragma unroll
                for (int j = 0; j < 8; j++) acc[i][j] += a[i]*b[j];
        }
        __syncthreads();
    }

    if (MODE == 0) {
        const int which = bn >> 9;
        float* dst = (which == 0) ? g_Q : (which == 1) ? g_K : g_V;
        const int cbase = bn & 511;
        const int c = cbase + tx*8;
        const int h = c >> 6, dd = c & 63;
        #pragma unroll
        for (int i = 0; i < 8; i++) {
            const int r = bm + ty*8 + i;
            const int bidx = r >> 11, nidx = r & (NSEQ-1);
            float* p = dst + (((size_t)bidx*HEADS + h)*NSEQ + nidx)*DH + dd;
            *(float4*)(p)   = make_float4(acc[i][0], acc[i][1], acc[i][2], acc[i][3]);
            *(float4*)(p+4) = make_float4(acc[i][4], acc[i][5], acc[i][6], acc[i][7]);
        }
    } else {
        float bz[8];
        *(float4*)(bz)   = *(const float4*)(bias + bn + tx*8);
        *(float4*)(bz+4) = *(const float4*)(bias + bn + tx*8 + 4);
        #pragma unroll
        for (int i = 0; i < 8; i++) {
            const int r = bm + ty*8 + i;
            float* yr = &g_Y[(size_t)r*DMODEL + bn + tx*8];
            *(float4*)(yr)   = make_float4(acc[i][0]+bz[0], acc[i][1]+bz[1],
                                           acc[i][2]+bz[2], acc[i][3]+bz[3]);
            *(float4*)(yr+4) = make_float4(acc[i][4]+bz[4], acc[i][5]+bz[5],
                                           acc[i][6]+bz[6], acc[i][7]+bz[7]);
        }
    }
}

// ---------------- scores: E = exp(scale*QK^T + decay) --------------------
// block = (ktile, qtile, bh), 128x128 output tile, K=64 single slab.
// Writes unnormalized E to attn buffer + per-(row,ktile) partial sums.
__global__ void __launch_bounds__(256, 2)
scores_kernel(float* __restrict__ attn)
{
    extern __shared__ float sm[];
    float* As = sm;             // Q^T swizzled [64][128]
    float* Bs = sm + 64*128;    // K^T swizzled [64][128]

    const int tid = threadIdx.x;
    const int kt = blockIdx.x, qt = blockIdx.y, bh = blockIdx.z;
    const int q0 = qt*128, k0 = kt*128;
    const float* Qb = g_Q + ((size_t)bh*NSEQ + q0)*DH;
    const float* Kb = g_K + ((size_t)bh*NSEQ + k0)*DH;

    // load + transpose with XOR swizzle (conflict-free STS)
    const int lr  = tid >> 2;       // 0..63
    const int seg = tid & 3;        // 16-float d segment
    const int sws = seg << 3;
    #pragma unroll
    for (int half = 0; half < 2; half++) {
        const int r = lr + half*64;
        const float* qs = Qb + (size_t)r*DH + seg*16;
        const float* ks = Kb + (size_t)r*DH + seg*16;
        float qv[16], kv[16];
        #pragma unroll
        for (int m = 0; m < 4; m++) {
            *(float4*)(qv + m*4) = *(const float4*)(qs + m*4);
            *(float4*)(kv + m*4) = *(const float4*)(ks + m*4);
        }
        const int col = r ^ sws;
        #pragma unroll
        for (int m = 0; m < 16; m++) {
            const int d = seg*16 + m;
            As[d*128 + col] = qv[m];
            Bs[d*128 + col] = kv[m];
        }
    }
    __syncthreads();

    const int ty = tid >> 4, tx = tid & 15;
    float acc[8][8];
    #pragma unroll
    for (int i = 0; i < 8; i++)
        #pragma unroll
        for (int j = 0; j < 8; j++) acc[i][j] = 0.f;

    #pragma unroll
    for (int ds = 0; ds < 4; ds++) {
        const int sw = ds << 3;
        const int ao = (ty*8) ^ sw;
        const int bo = (tx*8) ^ sw;
        #pragma unroll
        for (int dm = 0; dm < 16; dm++) {
            const int d = ds*16 + dm;
            float a[8], b[8];
            *(float4*)(a)   = *(const float4*)(As + d*128 + ao);
            *(float4*)(a+4) = *(const float4*)(As + d*128 + ao + 4);
            *(float4*)(b)   = *(const float4*)(Bs + d*128 + bo);
            *(float4*)(b+4) = *(const float4*)(Bs + d*128 + bo + 4);
            #pragma unroll
            for (int i = 0; i < 8; i++)
                #pragma unroll
                for (int j = 0; j < 8; j++) acc[i][j] += a[i]*b[j];
        }
    }

    // epilogue: exp(scale*s + exp(-k/50)), write E, accumulate row partials
    const float scale = 0.125f;
    float dec[8];
    #pragma unroll
    for (int j = 0; j < 8; j++)
        dec[j] = __expf(-(float)(k0 + tx*8 + j) * 0.02f);

    float psum[8];
    #pragma unroll
    for (int i = 0; i < 8; i++) {
        float e[8]; float s = 0.f;
        #pragma unroll
        for (int j = 0; j < 8; j++) {
            e[j] = __expf(fmaf(acc[i][j], scale, dec[j]));
            s += e[j];
        }
        psum[i] = s;
        float* p = attn + ((size_t)bh*NSEQ + q0 + ty*8 + i)*NSEQ + k0 + tx*8;
        *(float4*)(p)   = make_float4(e[0], e[1], e[2], e[3]);
        *(float4*)(p+4) = make_float4(e[4], e[5], e[6], e[7]);
    }
    // half-warp (16-lane) deterministic reduce over tx
    #pragma unroll
    for (int off = 1; off < 16; off <<= 1)
        #pragma unroll
        for (int i = 0; i < 8; i++)
            psum[i] += __shfl_xor_sync(0xffffffffu, psum[i], off);
    if ((tid & 15) == 0) {
        #pragma unroll
        for (int i = 0; i < 8; i++)
            g_part[((size_t)bh*16 + kt)*NSEQ + q0 + ty*8 + i] = psum[i];
    }
}

// ---------------- PV: normalize E in place + O = attn @ V -----------------
// block = (qtile 256, bh); k-tiles of 32; 8x8 microtile over [256q x 64d].
__global__ void __launch_bounds__(256, 2)
pv_kernel(float* __restrict__ attn)
{
    extern __shared__ float sm[];
    float* Es   = sm;               // [32][256] swizzled  32KB
    float* Vs   = sm + 32*256;      // [32][64]            8KB
    float* invs = Vs + 32*64;       // [256]

    const int tid = threadIdx.x;
    const int q0 = blockIdx.x * 256;
    const int bh = blockIdx.y;

    {   // deterministic rowsum from 16 partials
        float s = 0.f;
        #pragma unroll
        for (int p = 0; p < 16; p++)
            s += g_part[((size_t)bh*16 + p)*NSEQ + q0 + tid];
        invs[tid] = 1.0f / s;
    }
    __syncthreads();

    float* Ab = attn + ((size_t)bh*NSEQ + q0)*NSEQ;
    const float* Vb = g_V + (size_t)bh*NSEQ*DH;

    const int ty = tid >> 3, tx = tid & 7;     // FMA mapping: 32x8
    const int lr  = tid >> 1;                  // 0..127 (E rows per half)
    const int seg = tid & 1;                   // 16-k segment
    const int sws = seg << 4;
    const int lr2  = tid >> 3;                 // 0..31 (V rows)
    const int vseg = tid & 7;                  // 8-float segment

    float acc[8][8];
    #pragma unroll
    for (int i = 0; i < 8; i++)
        #pragma unroll
        for (int j = 0; j < 8; j++) acc[i][j] = 0.f;

    for (int kt = 0; kt < NSEQ/32; ++kt) {
        const int kb = kt*32;

        // prefetch into regs (no smem hazard before sync)
        float4 w0 = *(const float4*)(Vb + (size_t)(kb + lr2)*DH + vseg*8);
        float4 w1 = *(const float4*)(Vb + (size_t)(kb + lr2)*DH + vseg*8 + 4);

        float ev[2][16];
        #pragma unroll
        for (int half = 0; half < 2; half++) {
            const int row = half*128 + lr;
            const float inv = invs[row];
            float* ep = Ab + (size_t)row*NSEQ + kb + seg*16;
            #pragma unroll
            for (int m = 0; m < 4; m++) {
                float4 e = *(const float4*)(ep + m*4);
                e.x *= inv; e.y *= inv; e.z *= inv; e.w *= inv;
                *(float4*)(ep + m*4) = e;   // normalized attn (in-place, owned)
                ev[half][m*4+0] = e.x; ev[half][m*4+1] = e.y;
                ev[half][m*4+2] = e.z; ev[half][m*4+3] = e.w;
            }
        }
        __syncthreads();

        *(float4*)(Vs + lr2*64 + vseg*8)     = w0;
        *(float4*)(Vs + lr2*64 + vseg*8 + 4) = w1;
        #pragma unroll
        for (int half = 0; half < 2; half++) {
            const int row = half*128 + lr;
            const int col = row ^ sws;
            #pragma unroll
            for (int m = 0; m < 16; m++)
                Es[(seg*16 + m)*256 + col] = ev[half][m];
        }
        __syncthreads();

        #pragma unroll
        for (int ks = 0; ks < 2; ks++) {
            const int sw = ks << 4;
            const int ao = (ty*8) ^ sw;
            #pragma unroll
            for (int km = 0; km < 16; km++) {
                const int k = ks*16 + km;
                float a[8], b[8];
                *(float4*)(a)   = *(const float4*)(Es + k*256 + ao);
                *(float4*)(a+4) = *(const float4*)(Es + k*256 + ao + 4);
                *(float4*)(b)   = *(const float4*)(Vs + k*64 + tx*8);
                *(float4*)(b+4) = *(const float4*)(Vs + k*64 + tx*8 + 4);
                #pragma unroll
                for (int i = 0; i < 8; i++)
                    #pragma unroll
                    for (int j = 0; j < 8; j++) acc[i][j] += a[i]*b[j];
            }
        }
        __syncthreads();
    }

    // write O [b, n, dmodel] at head slot
    const int b = bh >> 3, h = bh & 7;
    #pragma unroll
    for (int i = 0; i < 8; i++) {
        const int q = q0 + ty*8 + i;
        float* op = g_O + ((size_t)(b*NSEQ + q))*DMODEL + h*DH + tx*8;
        *(float4*)(op)   = make_float4(acc[i][0], acc[i][1], acc[i][2], acc[i][3]);
        *(float4*)(op+4) = make_float4(acc[i][4], acc[i][5], acc[i][6], acc[i][7]);
    }
}

// ---------------- LayerNorm over 512 cols, one block per row --------------
__global__ void __launch_bounds__(256)
ln_kernel(const float* __restrict__ gamma, const float* __restrict__ beta,
          float* __restrict__ out)
{
    const int r = blockIdx.x, tid = threadIdx.x;
    const float* y = g_Y + (size_t)r*DMODEL;
    const float a = y[tid], b = y[tid + 256];
    float s  = a + b;
    float sq = a*a + b*b;
    #pragma unroll
    for (int off = 16; off; off >>= 1) {
        s  += __shfl_xor_sync(0xffffffffu, s,  off);
        sq += __shfl_xor_sync(0xffffffffu, sq, off);
    }
    __shared__ float ws[8], wq[8];
    __shared__ float mean_s, inv_s;
    if ((tid & 31) == 0) { ws[tid >> 5] = s; wq[tid >> 5] = sq; }
    __syncthreads();
    if (tid == 0) {
        float S = 0.f, Q = 0.f;
        #pragma unroll
        for (int i = 0; i < 8; i++) { S += ws[i]; Q += wq[i]; }
        const float mean = S * (1.0f/512.0f);
        const float var  = Q * (1.0f/512.0f) - mean*mean;
        mean_s = mean;
        inv_s  = rsqrtf(var + 1e-5f);
    }
    __syncthreads();
    out[(size_t)r*DMODEL + tid]       = (a - mean_s)*inv_s*gamma[tid]       + beta[tid];
    out[(size_t)r*DMODEL + tid + 256] = (b - mean_s)*inv_s*gamma[tid + 256] + beta[tid + 256];
}

// ---------------- launch ---------------------------------------------------
extern "C" void kernel_launch(void* const* d_in, const int* in_sizes, int n_in,
                              void* d_out, int out_size)
{
    const float* x        = (const float*)d_in[0];
    const float* w_qkv    = (const float*)d_in[1];
    const float* w_unify  = (const float*)d_in[2];
    const float* b_unify  = (const float*)d_in[3];
    const float* ln_gamma = (const float*)d_in[4];
    const float* ln_beta  = (const float*)d_in[5];

    float* out_ln   = (float*)d_out;
    float* out_attn = out_ln + (size_t)ROWS*DMODEL;

    cudaFuncSetAttribute(scores_kernel,
                         cudaFuncAttributeMaxDynamicSharedMemorySize, 65536);
    cudaFuncSetAttribute(pv_kernel,
                         cudaFuncAttributeMaxDynamicSharedMemorySize, 42240);

    // 1) QKV projection into [bh][n][dh]
    gemm_k512<0><<<dim3(12, 64), 256>>>(x, w_qkv, nullptr, 3*DMODEL);
    // 2) E = exp(scale*QK^T + decay) -> attn buffer (unnormalized) + partials
    scores_kernel<<<dim3(16, 16, 32), 256, 65536>>>(out_attn);
    // 3) normalize attn in place + O = attn @ V
    pv_kernel<<<dim3(8, 32), 256, 42240>>>(out_attn);
    // 4) unify GEMM + bias
    gemm_k512<1><<<dim3(4, 64), 256>>>(nullptr, w_unify, b_unify, DMODEL);
    // 5) LayerNorm -> first output
    ln_kernel<<<ROWS, 256>>>(ln_gamma, ln_beta, out_ln);
}

// round 5
// speedup vs baseline: 2.8264x; 1.2260x over previous
#include <cuda_runtime.h>
#include <cuda_bf16.h>
#include <cstdint>
#include <math.h>

#define HEADS   8
#define DH      64
#define NSEQ    2048
#define BATCH   4
#define DMODEL  512
#define ROWS    (BATCH*NSEQ)    // 8192
#define BHN     (BATCH*HEADS)   // 32

// ---------------- scratch (device globals; no allocations) ----------------
__device__ float g_Q[(size_t)BHN*NSEQ*DH];
__device__ float g_K[(size_t)BHN*NSEQ*DH];
__device__ float g_V[(size_t)BHN*NSEQ*DH];
__device__ float g_O[(size_t)ROWS*DMODEL];
__device__ float g_Y[(size_t)ROWS*DMODEL];
__device__ float g_part[(size_t)BHN*16*NSEQ];  // [bh][ktile][q] partial exp-sums

// ================= warp-level tensor core helpers (sm_80+ ISA) =============
__device__ __forceinline__ uint32_t smem_u32(const void* p) {
    uint32_t a;
    asm("{ .reg .u64 t; cvta.to.shared.u64 t, %1; cvt.u32.u64 %0, t; }"
        : "=r"(a) : "l"(p));
    return a;
}
__device__ __forceinline__ void ldsm4(uint32_t* r, uint32_t a) {
    asm volatile("ldmatrix.sync.aligned.m8n8.x4.shared.b16 {%0,%1,%2,%3}, [%4];"
        : "=r"(r[0]), "=r"(r[1]), "=r"(r[2]), "=r"(r[3]) : "r"(a));
}
__device__ __forceinline__ void ldsm2(uint32_t* r, uint32_t a) {
    asm volatile("ldmatrix.sync.aligned.m8n8.x2.shared.b16 {%0,%1}, [%2];"
        : "=r"(r[0]), "=r"(r[1]) : "r"(a));
}
__device__ __forceinline__ void ldsm2t(uint32_t* r, uint32_t a) {
    asm volatile("ldmatrix.sync.aligned.m8n8.x2.trans.shared.b16 {%0,%1}, [%2];"
        : "=r"(r[0]), "=r"(r[1]) : "r"(a));
}
__device__ __forceinline__ void mma16816(float* d, const uint32_t* a, const uint32_t* b) {
    asm volatile("mma.sync.aligned.m16n8k16.row.col.f32.bf16.bf16.f32 "
        "{%0,%1,%2,%3}, {%4,%5,%6,%7}, {%8,%9}, {%0,%1,%2,%3};"
        : "+f"(d[0]), "+f"(d[1]), "+f"(d[2]), "+f"(d[3])
        : "r"(a[0]), "r"(a[1]), "r"(a[2]), "r"(a[3]), "r"(b[0]), "r"(b[1]));
}

// split fp32 -> (hi, lo) bf16, packed as 2x uint32 (4 elems)
__device__ __forceinline__ void split_pack(float4 f, uint2& uh, uint2& ul) {
    __nv_bfloat16 h0 = __float2bfloat16(f.x), h1 = __float2bfloat16(f.y),
                  h2 = __float2bfloat16(f.z), h3 = __float2bfloat16(f.w);
    __nv_bfloat16 l0 = __float2bfloat16(f.x - __bfloat162float(h0));
    __nv_bfloat16 l1 = __float2bfloat16(f.y - __bfloat162float(h1));
    __nv_bfloat16 l2 = __float2bfloat16(f.z - __bfloat162float(h2));
    __nv_bfloat16 l3 = __float2bfloat16(f.w - __bfloat162float(h3));
    uh.x = (uint32_t)__bfloat16_as_ushort(h0) | ((uint32_t)__bfloat16_as_ushort(h1) << 16);
    uh.y = (uint32_t)__bfloat16_as_ushort(h2) | ((uint32_t)__bfloat16_as_ushort(h3) << 16);
    ul.x = (uint32_t)__bfloat16_as_ushort(l0) | ((uint32_t)__bfloat16_as_ushort(l1) << 16);
    ul.y = (uint32_t)__bfloat16_as_ushort(l2) | ((uint32_t)__bfloat16_as_ushort(l3) << 16);
}

// ---------------- generic K=512 SGEMM (unchanged, known good) -------------
template<int MODE>
__global__ void __launch_bounds__(256)
gemm_k512(const float* __restrict__ A_in, const float* __restrict__ B,
          const float* __restrict__ bias, int ldb)
{
    __shared__ float As[8][128];
    __shared__ float Bs[8][128];
    const float* A = (MODE == 0) ? A_in : g_O;

    const int bm = blockIdx.y * 128;
    const int bn = blockIdx.x * 128;
    const int tid = threadIdx.x;
    const int ty = tid >> 4, tx = tid & 15;
    const int lrow = tid >> 1, lseg = (tid & 1) << 2;
    const int brow = tid >> 5, bcol = (tid & 31) << 2;

    float acc[8][8];
    #pragma unroll
    for (int i = 0; i < 8; i++)
        #pragma unroll
        for (int j = 0; j < 8; j++) acc[i][j] = 0.f;

    for (int k0 = 0; k0 < 512; k0 += 8) {
        float4 av = *(const float4*)(A + (size_t)(bm + lrow)*512 + k0 + lseg);
        float4 bv = *(const float4*)(B + (size_t)(k0 + brow)*ldb + bn + bcol);
        As[lseg+0][lrow] = av.x; As[lseg+1][lrow] = av.y;
        As[lseg+2][lrow] = av.z; As[lseg+3][lrow] = av.w;
        *(float4*)&Bs[brow][bcol] = bv;
        __syncthreads();
        #pragma unroll
        for (int k = 0; k < 8; k++) {
            float a[8], b[8];
            *(float4*)(a)   = *(const float4*)&As[k][ty*8];
            *(float4*)(a+4) = *(const float4*)&As[k][ty*8+4];
            *(float4*)(b)   = *(const float4*)&Bs[k][tx*8];
            *(float4*)(b+4) = *(const float4*)&Bs[k][tx*8+4];
            #pragma unroll
            for (int i = 0; i < 8; i++)
                #pragma unroll
                for (int j = 0; j < 8; j++) acc[i][j] += a[i]*b[j];
        }
        __syncthreads();
    }

    if (MODE == 0) {
        const int which = bn >> 9;
        float* dst = (which == 0) ? g_Q : (which == 1) ? g_K : g_V;
        const int cbase = bn & 511;
        const int c = cbase + tx*8;
        const int h = c >> 6, dd = c & 63;
        #pragma unroll
        for (int i = 0; i < 8; i++) {
            const int r = bm + ty*8 + i;
            const int bidx = r >> 11, nidx = r & (NSEQ-1);
            float* p = dst + (((size_t)bidx*HEADS + h)*NSEQ + nidx)*DH + dd;
            *(float4*)(p)   = make_float4(acc[i][0], acc[i][1], acc[i][2], acc[i][3]);
            *(float4*)(p+4) = make_float4(acc[i][4], acc[i][5], acc[i][6], acc[i][7]);
        }
    } else {
        float bz[8];
        *(float4*)(bz)   = *(const float4*)(bias + bn + tx*8);
        *(float4*)(bz+4) = *(const float4*)(bias + bn + tx*8 + 4);
        #pragma unroll
        for (int i = 0; i < 8; i++) {
            const int r = bm + ty*8 + i;
            float* yr = &g_Y[(size_t)r*DMODEL + bn + tx*8];
            *(float4*)(yr)   = make_float4(acc[i][0]+bz[0], acc[i][1]+bz[1],
                                           acc[i][2]+bz[2], acc[i][3]+bz[3]);
            *(float4*)(yr+4) = make_float4(acc[i][4]+bz[4], acc[i][5]+bz[5],
                                           acc[i][6]+bz[6], acc[i][7]+bz[7]);
        }
    }
}

// ============ scores: E = exp(scale*QK^T + decay) via mma.sync =============
// block = (kt, qt, bh): 128x128 tile, K=64.
// smem: Qhi/Qlo/Khi/Klo as bf16 [128][64] with row stride 72 elems (144 B).
#define SC_QH   0
#define SC_QL   18432
#define SC_KH   36864
#define SC_KL   55296
#define SC_PS   73728
#define SC_SMEM (73728 + 1024)

__global__ void __launch_bounds__(256)
scores_mma(float* __restrict__ attn)
{
    extern __shared__ char sm[];
    const uint32_t smb = smem_u32(sm);
    const int tid = threadIdx.x;
    const int wid = tid >> 5, lane = tid & 31;
    const int kt = blockIdx.x, qt = blockIdx.y, bh = blockIdx.z;
    const int q0 = qt*128, k0 = kt*128;

    // ---- stage Q/K tiles as split bf16 ----
    const float* Qb = g_Q + ((size_t)bh*NSEQ + q0)*DH;
    const float* Kb = g_K + ((size_t)bh*NSEQ + k0)*DH;
    #pragma unroll
    for (int i = 0; i < 8; i++) {
        const int f = i*256 + tid;           // 0..2047
        const int row = f >> 4, c4 = (f & 15)*4;
        const int boff = row*144 + c4*2;
        uint2 uh, ul;
        split_pack(*(const float4*)(Qb + (size_t)row*DH + c4), uh, ul);
        *(uint2*)(sm + SC_QH + boff) = uh;
        *(uint2*)(sm + SC_QL + boff) = ul;
        split_pack(*(const float4*)(Kb + (size_t)row*DH + c4), uh, ul);
        *(uint2*)(sm + SC_KH + boff) = uh;
        *(uint2*)(sm + SC_KL + boff) = ul;
    }
    __syncthreads();

    // ---- warp tiles: 32 q-rows x 64 k-cols ----
    const int mw = (wid & 3)*32, nw = (wid >> 2)*64;
    const int l15 = lane & 15, l7 = lane & 7;
    const int lh = (lane >> 3) & 1, lq = lane >> 4;

    float acc[2][8][4];
    #pragma unroll
    for (int mf = 0; mf < 2; mf++)
        #pragma unroll
        for (int nf = 0; nf < 8; nf++)
            #pragma unroll
            for (int e = 0; e < 4; e++) acc[mf][nf][e] = 0.f;

    #pragma unroll
    for (int ks = 0; ks < 4; ks++) {
        uint32_t ah[2][4], al[2][4];
        #pragma unroll
        for (int mf = 0; mf < 2; mf++) {
            const uint32_t ao = (mw + mf*16 + l15)*144 + (ks*16 + lq*8)*2;
            ldsm4(ah[mf], smb + SC_QH + ao);
            ldsm4(al[mf], smb + SC_QL + ao);
        }
        #pragma unroll
        for (int nf = 0; nf < 8; nf++) {
            const uint32_t bo = (nw + nf*8 + l7)*144 + (ks*16 + lh*8)*2;
            uint32_t bhf[2], blf[2];
            ldsm2(bhf, smb + SC_KH + bo);
            ldsm2(blf, smb + SC_KL + bo);
            #pragma unroll
            for (int mf = 0; mf < 2; mf++) {
                mma16816(acc[mf][nf], ah[mf], bhf);
                mma16816(acc[mf][nf], ah[mf], blf);
                mma16816(acc[mf][nf], al[mf], bhf);
            }
        }
    }

    // ---- epilogue: exp(0.125*s + decay), write E, row partial sums ----
    const int g = lane >> 2, cq = (lane & 3)*2;
    float psum[2][2] = {{0.f, 0.f}, {0.f, 0.f}};
    #pragma unroll
    for (int mf = 0; mf < 2; mf++) {
        const int r0 = mw + mf*16 + g;
        #pragma unroll
        for (int nf = 0; nf < 8; nf++) {
            const int c = nw + nf*8 + cq;
            const float dec0 = __expf((float)(k0 + c)     * -0.02f);
            const float dec1 = __expf((float)(k0 + c + 1) * -0.02f);
            const float e0 = __expf(fmaf(acc[mf][nf][0], 0.125f, dec0));
            const float e1 = __expf(fmaf(acc[mf][nf][1], 0.125f, dec1));
            const float e2 = __expf(fmaf(acc[mf][nf][2], 0.125f, dec0));
            const float e3 = __expf(fmaf(acc[mf][nf][3], 0.125f, dec1));
            float* p = attn + ((size_t)bh*NSEQ + q0 + r0)*NSEQ + k0 + c;
            *(float2*)(p)            = make_float2(e0, e1);
            *(float2*)(p + 8*NSEQ)   = make_float2(e2, e3);
            psum[mf][0] += e0 + e1;
            psum[mf][1] += e2 + e3;
        }
    }
    #pragma unroll
    for (int off = 1; off < 4; off <<= 1) {
        psum[0][0] += __shfl_xor_sync(0xffffffffu, psum[0][0], off);
        psum[0][1] += __shfl_xor_sync(0xffffffffu, psum[0][1], off);
        psum[1][0] += __shfl_xor_sync(0xffffffffu, psum[1][0], off);
        psum[1][1] += __shfl_xor_sync(0xffffffffu, psum[1][1], off);
    }
    float* ps = (float*)(sm + SC_PS);
    if ((lane & 3) == 0) {
        #pragma unroll
        for (int mf = 0; mf < 2; mf++)
            #pragma unroll
            for (int h = 0; h < 2; h++)
                ps[wid*32 + mf*16 + h*8 + g] = psum[mf][h];
    }
    __syncthreads();
    if (tid < 128) {
        const float tot = ps[(tid >> 5)*32 + (tid & 31)]
                        + ps[((tid >> 5) + 4)*32 + (tid & 31)];
        g_part[((size_t)bh*16 + kt)*NSEQ + q0 + tid] = tot;
    }
}

// ======== PV: normalize E in place + O = P @ V via mma.sync ================
// block = (qt, bh): O tile 128 q x 64 d, looping 32 slabs of 64 keys.
#define PV_PH   0
#define PV_PL   18432
#define PV_VH   36864
#define PV_VL   46080
#define PV_INV  55296
#define PV_SMEM (55296 + 512)

__global__ void __launch_bounds__(256)
pv_mma(float* __restrict__ attn)
{
    extern __shared__ char sm[];
    const uint32_t smb = smem_u32(sm);
    float* invs = (float*)(sm + PV_INV);
    const int tid = threadIdx.x;
    const int wid = tid >> 5, lane = tid & 31;
    const int q0 = blockIdx.x * 128;
    const int bh = blockIdx.y;

    if (tid < 128) {
        float s = 0.f;
        #pragma unroll
        for (int p = 0; p < 16; p++)
            s += g_part[((size_t)bh*16 + p)*NSEQ + q0 + tid];
        invs[tid] = 1.0f / s;
    }
    __syncthreads();

    float* Ab = attn + ((size_t)bh*NSEQ + q0)*NSEQ;
    const float* Vb = g_V + (size_t)bh*NSEQ*DH;

    const int wq = (wid & 3)*32, wd = (wid >> 2)*32;
    const int l15 = lane & 15;
    const int lq = lane >> 4;
    const int g = lane >> 2, cq = (lane & 3)*2;

    float acc[2][4][4];
    #pragma unroll
    for (int mf = 0; mf < 2; mf++)
        #pragma unroll
        for (int nf = 0; nf < 4; nf++)
            #pragma unroll
            for (int e = 0; e < 4; e++) acc[mf][nf][e] = 0.f;

    for (int kt = 0; kt < 32; ++kt) {
        const int kb = kt*64;

        // E load + fp32 normalize + attn writeback; V slab (64x64) load
        float4 ev[8];
        #pragma unroll
        for (int i = 0; i < 8; i++) {
            const int f = i*256 + tid;
            const int row = f >> 4, c4 = (f & 15)*4;
            float* ep = Ab + (size_t)row*NSEQ + kb + c4;
            float4 e = *(const float4*)ep;
            const float inv = invs[row];
            e.x *= inv; e.y *= inv; e.z *= inv; e.w *= inv;
            *(float4*)ep = e;
            ev[i] = e;
        }
        float4 vv[4];
        #pragma unroll
        for (int i = 0; i < 4; i++) {
            const int f = i*256 + tid;
            vv[i] = *(const float4*)(Vb + (size_t)(kb + (f >> 4))*DH + (f & 15)*4);
        }

        __syncthreads();   // prior slab's ldmatrix reads done

        #pragma unroll
        for (int i = 0; i < 8; i++) {
            const int f = i*256 + tid;
            const int boff = (f >> 4)*144 + (f & 15)*8;
            uint2 uh, ul;
            split_pack(ev[i], uh, ul);
            *(uint2*)(sm + PV_PH + boff) = uh;
            *(uint2*)(sm + PV_PL + boff) = ul;
        }
        #pragma unroll
        for (int i = 0; i < 4; i++) {
            const int f = i*256 + tid;
            const int boff = (f >> 4)*144 + (f & 15)*8;
            uint2 uh, ul;
            split_pack(vv[i], uh, ul);
            *(uint2*)(sm + PV_VH + boff) = uh;
            *(uint2*)(sm + PV_VL + boff) = ul;
        }
        __syncthreads();

        #pragma unroll
        for (int ks = 0; ks < 4; ks++) {
            uint32_t ah[2][4], al[2][4];
            #pragma unroll
            for (int mf = 0; mf < 2; mf++) {
                const uint32_t ao = (wq + mf*16 + l15)*144 + (ks*16 + lq*8)*2;
                ldsm4(ah[mf], smb + PV_PH + ao);
                ldsm4(al[mf], smb + PV_PL + ao);
            }
            #pragma unroll
            for (int nf = 0; nf < 4; nf++) {
                const uint32_t bo = (ks*16 + l15)*144 + (wd + nf*8)*2;
                uint32_t bhf[2], blf[2];
                ldsm2t(bhf, smb + PV_VH + bo);
                ldsm2t(blf, smb + PV_VL + bo);
                #pragma unroll
                for (int mf = 0; mf < 2; mf++) {
                    mma16816(acc[mf][nf], ah[mf], bhf);
                    mma16816(acc[mf][nf], ah[mf], blf);
                    mma16816(acc[mf][nf], al[mf], bhf);
                }
            }
        }
    }

    // write O into g_O [b][n][dmodel] at head slot
    const int b = bh >> 3, h = bh & 7;
    #pragma unroll
    for (int mf = 0; mf < 2; mf++) {
        const int r0 = q0 + wq + mf*16 + g;
        #pragma unroll
        for (int nf = 0; nf < 4; nf++) {
            const int col = h*DH + wd + nf*8 + cq;
            float* op = g_O + (size_t)(b*NSEQ + r0)*DMODEL + col;
            *(float2*)(op)            = make_float2(acc[mf][nf][0], acc[mf][nf][1]);
            *(float2*)(op + 8*DMODEL) = make_float2(acc[mf][nf][2], acc[mf][nf][3]);
        }
    }
}

// ---------------- LayerNorm (unchanged) -----------------------------------
__global__ void __launch_bounds__(256)
ln_kernel(const float* __restrict__ gamma, const float* __restrict__ beta,
          float* __restrict__ out)
{
    const int r = blockIdx.x, tid = threadIdx.x;
    const float* y = g_Y + (size_t)r*DMODEL;
    const float a = y[tid], b = y[tid + 256];
    float s  = a + b;
    float sq = a*a + b*b;
    #pragma unroll
    for (int off = 16; off; off >>= 1) {
        s  += __shfl_xor_sync(0xffffffffu, s,  off);
        sq += __shfl_xor_sync(0xffffffffu, sq, off);
    }
    __shared__ float ws[8], wq[8];
    __shared__ float mean_s, inv_s;
    if ((tid & 31) == 0) { ws[tid >> 5] = s; wq[tid >> 5] = sq; }
    __syncthreads();
    if (tid == 0) {
        float S = 0.f, Q = 0.f;
        #pragma unroll
        for (int i = 0; i < 8; i++) { S += ws[i]; Q += wq[i]; }
        const float mean = S * (1.0f/512.0f);
        const float var  = Q * (1.0f/512.0f) - mean*mean;
        mean_s = mean;
        inv_s  = rsqrtf(var + 1e-5f);
    }
    __syncthreads();
    out[(size_t)r*DMODEL + tid]       = (a - mean_s)*inv_s*gamma[tid]       + beta[tid];
    out[(size_t)r*DMODEL + tid + 256] = (b - mean_s)*inv_s*gamma[tid + 256] + beta[tid + 256];
}

// ---------------- launch ---------------------------------------------------
extern "C" void kernel_launch(void* const* d_in, const int* in_sizes, int n_in,
                              void* d_out, int out_size)
{
    const float* x        = (const float*)d_in[0];
    const float* w_qkv    = (const float*)d_in[1];
    const float* w_unify  = (const float*)d_in[2];
    const float* b_unify  = (const float*)d_in[3];
    const float* ln_gamma = (const float*)d_in[4];
    const float* ln_beta  = (const float*)d_in[5];

    float* out_ln   = (float*)d_out;
    float* out_attn = out_ln + (size_t)ROWS*DMODEL;

    cudaFuncSetAttribute(scores_mma, cudaFuncAttributeMaxDynamicSharedMemorySize, SC_SMEM);
    cudaFuncSetAttribute(pv_mma,     cudaFuncAttributeMaxDynamicSharedMemorySize, PV_SMEM);

    // 1) QKV projection into [bh][n][dh]
    gemm_k512<0><<<dim3(12, 64), 256>>>(x, w_qkv, nullptr, 3*DMODEL);
    // 2) E = exp(scale*QK^T + decay) -> attn (unnormalized) + partials
    scores_mma<<<dim3(16, 16, 32), 256, SC_SMEM>>>(out_attn);
    // 3) normalize attn in place + O = P @ V
    pv_mma<<<dim3(16, 32), 256, PV_SMEM>>>(out_attn);
    // 4) unify GEMM + bias
    gemm_k512<1><<<dim3(4, 64), 256>>>(nullptr, w_unify, b_unify, DMODEL);
    // 5) LayerNorm -> first output
    ln_kernel<<<ROWS, 256>>>(ln_gamma, ln_beta, out_ln);
}

// round 6
// speedup vs baseline: 3.4403x; 1.2172x over previous
#include <cuda_runtime.h>
#include <cuda_bf16.h>
#include <cstdint>
#include <math.h>

#define HEADS   8
#define DH      64
#define NSEQ    2048
#define BATCH   4
#define DMODEL  512
#define ROWS    (BATCH*NSEQ)    // 8192
#define BHN     (BATCH*HEADS)   // 32

// ---------------- scratch (device globals; no allocations) ----------------
__device__ float g_Q[(size_t)BHN*NSEQ*DH];
__device__ float g_K[(size_t)BHN*NSEQ*DH];
__device__ float g_V[(size_t)BHN*NSEQ*DH];
__device__ float g_O[(size_t)ROWS*DMODEL];
__device__ float g_Y[(size_t)ROWS*DMODEL];
__device__ float g_part[(size_t)BHN*16*NSEQ];  // [bh][ktile][q] partial exp-sums

// ================= warp-level tensor core helpers (sm_80+ ISA) =============
__device__ __forceinline__ uint32_t smem_u32(const void* p) {
    uint32_t a;
    asm("{ .reg .u64 t; cvta.to.shared.u64 t, %1; cvt.u32.u64 %0, t; }"
        : "=r"(a) : "l"(p));
    return a;
}
__device__ __forceinline__ void ldsm4(uint32_t* r, uint32_t a) {
    asm volatile("ldmatrix.sync.aligned.m8n8.x4.shared.b16 {%0,%1,%2,%3}, [%4];"
        : "=r"(r[0]), "=r"(r[1]), "=r"(r[2]), "=r"(r[3]) : "r"(a));
}
__device__ __forceinline__ void ldsm2(uint32_t* r, uint32_t a) {
    asm volatile("ldmatrix.sync.aligned.m8n8.x2.shared.b16 {%0,%1}, [%2];"
        : "=r"(r[0]), "=r"(r[1]) : "r"(a));
}
__device__ __forceinline__ void ldsm2t(uint32_t* r, uint32_t a) {
    asm volatile("ldmatrix.sync.aligned.m8n8.x2.trans.shared.b16 {%0,%1}, [%2];"
        : "=r"(r[0]), "=r"(r[1]) : "r"(a));
}
__device__ __forceinline__ void mma16816(float* d, const uint32_t* a, const uint32_t* b) {
    asm volatile("mma.sync.aligned.m16n8k16.row.col.f32.bf16.bf16.f32 "
        "{%0,%1,%2,%3}, {%4,%5,%6,%7}, {%8,%9}, {%0,%1,%2,%3};"
        : "+f"(d[0]), "+f"(d[1]), "+f"(d[2]), "+f"(d[3])
        : "r"(a[0]), "r"(a[1]), "r"(a[2]), "r"(a[3]), "r"(b[0]), "r"(b[1]));
}

// split fp32 -> (hi, lo) bf16, packed as 2x uint32 (4 elems)
__device__ __forceinline__ void split_pack(float4 f, uint2& uh, uint2& ul) {
    __nv_bfloat16 h0 = __float2bfloat16(f.x), h1 = __float2bfloat16(f.y),
                  h2 = __float2bfloat16(f.z), h3 = __float2bfloat16(f.w);
    __nv_bfloat16 l0 = __float2bfloat16(f.x - __bfloat162float(h0));
    __nv_bfloat16 l1 = __float2bfloat16(f.y - __bfloat162float(h1));
    __nv_bfloat16 l2 = __float2bfloat16(f.z - __bfloat162float(h2));
    __nv_bfloat16 l3 = __float2bfloat16(f.w - __bfloat162float(h3));
    uh.x = (uint32_t)__bfloat16_as_ushort(h0) | ((uint32_t)__bfloat16_as_ushort(h1) << 16);
    uh.y = (uint32_t)__bfloat16_as_ushort(h2) | ((uint32_t)__bfloat16_as_ushort(h3) << 16);
    ul.x = (uint32_t)__bfloat16_as_ushort(l0) | ((uint32_t)__bfloat16_as_ushort(l1) << 16);
    ul.y = (uint32_t)__bfloat16_as_ushort(l2) | ((uint32_t)__bfloat16_as_ushort(l3) << 16);
}

// ======== HMMA projection GEMM: C[128x128/tile] = A[M,512] @ B[512,N] ======
// MODE 0: A = x, B = w_qkv (ldb=1536) -> scatter into g_Q/g_K/g_V
// MODE 1: A = g_O, B = w_unify (ldb=512) -> + bias -> g_Y
// smem: Ahi/Alo [128][72] bf16 (stride 144 B), Bhi/Blo [64][136] bf16 (272 B)
#define GM_AH   0
#define GM_AL   18432
#define GM_BH   36864
#define GM_BL   54272
#define GM_SMEM 71680

template<int MODE>
__global__ void __launch_bounds__(256)
gemm_hmma(const float* __restrict__ A_in, const float* __restrict__ B,
          const float* __restrict__ bias, int ldb)
{
    extern __shared__ char sm[];
    const uint32_t smb = smem_u32(sm);
    const float* A = (MODE == 0) ? A_in : g_O;

    const int bm = blockIdx.y * 128;
    const int bn = blockIdx.x * 128;
    const int tid = threadIdx.x;
    const int wid = tid >> 5, lane = tid & 31;

    const int wq = (wid & 3)*32, nw = (wid >> 2)*64;
    const int l15 = lane & 15;
    const int lq = lane >> 4;
    const int g = lane >> 2, cq = (lane & 3)*2;

    float acc[2][8][4];
    #pragma unroll
    for (int mf = 0; mf < 2; mf++)
        #pragma unroll
        for (int nf = 0; nf < 8; nf++)
            #pragma unroll
            for (int e = 0; e < 4; e++) acc[mf][nf][e] = 0.f;

    for (int ks0 = 0; ks0 < 8; ++ks0) {
        const int k0 = ks0*64;

        // prefetch A slab (128x64) and B slab (64x128) into regs
        float4 av[8], bv[8];
        #pragma unroll
        for (int i = 0; i < 8; i++) {
            const int f = i*256 + tid;
            av[i] = *(const float4*)(A + (size_t)(bm + (f >> 4))*512 + k0 + (f & 15)*4);
        }
        #pragma unroll
        for (int i = 0; i < 8; i++) {
            const int f = i*256 + tid;
            bv[i] = *(const float4*)(B + (size_t)(k0 + (f >> 5))*ldb + bn + (f & 31)*4);
        }

        __syncthreads();   // prior slab's ldmatrix reads done

        #pragma unroll
        for (int i = 0; i < 8; i++) {
            const int f = i*256 + tid;
            const int boff = (f >> 4)*144 + (f & 15)*8;
            uint2 uh, ul;
            split_pack(av[i], uh, ul);
            *(uint2*)(sm + GM_AH + boff) = uh;
            *(uint2*)(sm + GM_AL + boff) = ul;
        }
        #pragma unroll
        for (int i = 0; i < 8; i++) {
            const int f = i*256 + tid;
            const int boff = (f >> 5)*272 + (f & 31)*8;
            uint2 uh, ul;
            split_pack(bv[i], uh, ul);
            *(uint2*)(sm + GM_BH + boff) = uh;
            *(uint2*)(sm + GM_BL + boff) = ul;
        }
        __syncthreads();

        #pragma unroll
        for (int ks = 0; ks < 4; ks++) {
            uint32_t ah[2][4], al[2][4];
            #pragma unroll
            for (int mf = 0; mf < 2; mf++) {
                const uint32_t ao = (wq + mf*16 + l15)*144 + (ks*16 + lq*8)*2;
                ldsm4(ah[mf], smb + GM_AH + ao);
                ldsm4(al[mf], smb + GM_AL + ao);
            }
            #pragma unroll
            for (int nf = 0; nf < 8; nf++) {
                const uint32_t bo = (ks*16 + l15)*272 + (nw + nf*8)*2;
                uint32_t bhf[2], blf[2];
                ldsm2t(bhf, smb + GM_BH + bo);
                ldsm2t(blf, smb + GM_BL + bo);
                #pragma unroll
                for (int mf = 0; mf < 2; mf++) {
                    mma16816(acc[mf][nf], ah[mf], bhf);
                    mma16816(acc[mf][nf], ah[mf], blf);
                    mma16816(acc[mf][nf], al[mf], bhf);
                }
            }
        }
    }

    // ---- epilogue ----
    if (MODE == 0) {
        const int which = bn >> 9;
        float* dst = (which == 0) ? g_Q : (which == 1) ? g_K : g_V;
        const int cbase = bn & 511;
        #pragma unroll
        for (int mf = 0; mf < 2; mf++) {
            const int r = bm + wq + mf*16 + g;
            const int bidx = r >> 11, nidx = r & (NSEQ-1);
            #pragma unroll
            for (int nf = 0; nf < 8; nf++) {
                const int cb = cbase + nw + nf*8 + cq;
                const int h = cb >> 6, dd = cb & 63;
                float* p = dst + (((size_t)bidx*HEADS + h)*NSEQ + nidx)*DH + dd;
                *(float2*)(p)        = make_float2(acc[mf][nf][0], acc[mf][nf][1]);
                *(float2*)(p + 8*DH) = make_float2(acc[mf][nf][2], acc[mf][nf][3]);
            }
        }
    } else {
        #pragma unroll
        for (int mf = 0; mf < 2; mf++) {
            const int r = bm + wq + mf*16 + g;
            #pragma unroll
            for (int nf = 0; nf < 8; nf++) {
                const int col = bn + nw + nf*8 + cq;
                const float b0 = bias[col], b1 = bias[col + 1];
                float* yr = g_Y + (size_t)r*DMODEL + col;
                *(float2*)(yr)            = make_float2(acc[mf][nf][0] + b0,
                                                        acc[mf][nf][1] + b1);
                *(float2*)(yr + 8*DMODEL) = make_float2(acc[mf][nf][2] + b0,
                                                        acc[mf][nf][3] + b1);
            }
        }
    }
}

// ============ scores: E = exp(scale*QK^T + decay) via mma.sync =============
#define SC_QH   0
#define SC_QL   18432
#define SC_KH   36864
#define SC_KL   55296
#define SC_PS   73728
#define SC_SMEM (73728 + 1024)

__global__ void __launch_bounds__(256)
scores_mma(float* __restrict__ attn)
{
    extern __shared__ char sm[];
    const uint32_t smb = smem_u32(sm);
    const int tid = threadIdx.x;
    const int wid = tid >> 5, lane = tid & 31;
    const int kt = blockIdx.x, qt = blockIdx.y, bh = blockIdx.z;
    const int q0 = qt*128, k0 = kt*128;

    const float* Qb = g_Q + ((size_t)bh*NSEQ + q0)*DH;
    const float* Kb = g_K + ((size_t)bh*NSEQ + k0)*DH;
    #pragma unroll
    for (int i = 0; i < 8; i++) {
        const int f = i*256 + tid;
        const int row = f >> 4, c4 = (f & 15)*4;
        const int boff = row*144 + c4*2;
        uint2 uh, ul;
        split_pack(*(const float4*)(Qb + (size_t)row*DH + c4), uh, ul);
        *(uint2*)(sm + SC_QH + boff) = uh;
        *(uint2*)(sm + SC_QL + boff) = ul;
        split_pack(*(const float4*)(Kb + (size_t)row*DH + c4), uh, ul);
        *(uint2*)(sm + SC_KH + boff) = uh;
        *(uint2*)(sm + SC_KL + boff) = ul;
    }
    __syncthreads();

    const int mw = (wid & 3)*32, nw = (wid >> 2)*64;
    const int l15 = lane & 15, l7 = lane & 7;
    const int lh = (lane >> 3) & 1, lq = lane >> 4;

    float acc[2][8][4];
    #pragma unroll
    for (int mf = 0; mf < 2; mf++)
        #pragma unroll
        for (int nf = 0; nf < 8; nf++)
            #pragma unroll
            for (int e = 0; e < 4; e++) acc[mf][nf][e] = 0.f;

    #pragma unroll
    for (int ks = 0; ks < 4; ks++) {
        uint32_t ah[2][4], al[2][4];
        #pragma unroll
        for (int mf = 0; mf < 2; mf++) {
            const uint32_t ao = (mw + mf*16 + l15)*144 + (ks*16 + lq*8)*2;
            ldsm4(ah[mf], smb + SC_QH + ao);
            ldsm4(al[mf], smb + SC_QL + ao);
        }
        #pragma unroll
        for (int nf = 0; nf < 8; nf++) {
            const uint32_t bo = (nw + nf*8 + l7)*144 + (ks*16 + lh*8)*2;
            uint32_t bhf[2], blf[2];
            ldsm2(bhf, smb + SC_KH + bo);
            ldsm2(blf, smb + SC_KL + bo);
            #pragma unroll
            for (int mf = 0; mf < 2; mf++) {
                mma16816(acc[mf][nf], ah[mf], bhf);
                mma16816(acc[mf][nf], ah[mf], blf);
                mma16816(acc[mf][nf], al[mf], bhf);
            }
        }
    }

    const int g = lane >> 2, cq = (lane & 3)*2;
    float psum[2][2] = {{0.f, 0.f}, {0.f, 0.f}};
    #pragma unroll
    for (int mf = 0; mf < 2; mf++) {
        const int r0 = mw + mf*16 + g;
        #pragma unroll
        for (int nf = 0; nf < 8; nf++) {
            const int c = nw + nf*8 + cq;
            const float dec0 = __expf((float)(k0 + c)     * -0.02f);
            const float dec1 = __expf((float)(k0 + c + 1) * -0.02f);
            const float e0 = __expf(fmaf(acc[mf][nf][0], 0.125f, dec0));
            const float e1 = __expf(fmaf(acc[mf][nf][1], 0.125f, dec1));
            const float e2 = __expf(fmaf(acc[mf][nf][2], 0.125f, dec0));
            const float e3 = __expf(fmaf(acc[mf][nf][3], 0.125f, dec1));
            float* p = attn + ((size_t)bh*NSEQ + q0 + r0)*NSEQ + k0 + c;
            *(float2*)(p)            = make_float2(e0, e1);
            *(float2*)(p + 8*NSEQ)   = make_float2(e2, e3);
            psum[mf][0] += e0 + e1;
            psum[mf][1] += e2 + e3;
        }
    }
    #pragma unroll
    for (int off = 1; off < 4; off <<= 1) {
        psum[0][0] += __shfl_xor_sync(0xffffffffu, psum[0][0], off);
        psum[0][1] += __shfl_xor_sync(0xffffffffu, psum[0][1], off);
        psum[1][0] += __shfl_xor_sync(0xffffffffu, psum[1][0], off);
        psum[1][1] += __shfl_xor_sync(0xffffffffu, psum[1][1], off);
    }
    float* ps = (float*)(sm + SC_PS);
    if ((lane & 3) == 0) {
        #pragma unroll
        for (int mf = 0; mf < 2; mf++)
            #pragma unroll
            for (int h = 0; h < 2; h++)
                ps[wid*32 + mf*16 + h*8 + g] = psum[mf][h];
    }
    __syncthreads();
    if (tid < 128) {
        const float tot = ps[(tid >> 5)*32 + (tid & 31)]
                        + ps[((tid >> 5) + 4)*32 + (tid & 31)];
        g_part[((size_t)bh*16 + kt)*NSEQ + q0 + tid] = tot;
    }
}

// ======== PV: normalize E in place + O = P @ V via mma.sync ================
#define PV_PH   0
#define PV_PL   18432
#define PV_VH   36864
#define PV_VL   46080
#define PV_INV  55296
#define PV_SMEM (55296 + 512)

__global__ void __launch_bounds__(256)
pv_mma(float* __restrict__ attn)
{
    extern __shared__ char sm[];
    const uint32_t smb = smem_u32(sm);
    float* invs = (float*)(sm + PV_INV);
    const int tid = threadIdx.x;
    const int wid = tid >> 5, lane = tid & 31;
    const int q0 = blockIdx.x * 128;
    const int bh = blockIdx.y;

    if (tid < 128) {
        float s = 0.f;
        #pragma unroll
        for (int p = 0; p < 16; p++)
            s += g_part[((size_t)bh*16 + p)*NSEQ + q0 + tid];
        invs[tid] = 1.0f / s;
    }
    __syncthreads();

    float* Ab = attn + ((size_t)bh*NSEQ + q0)*NSEQ;
    const float* Vb = g_V + (size_t)bh*NSEQ*DH;

    const int wq = (wid & 3)*32, wd = (wid >> 2)*32;
    const int l15 = lane & 15;
    const int lq = lane >> 4;
    const int g = lane >> 2, cq = (lane & 3)*2;

    float acc[2][4][4];
    #pragma unroll
    for (int mf = 0; mf < 2; mf++)
        #pragma unroll
        for (int nf = 0; nf < 4; nf++)
            #pragma unroll
            for (int e = 0; e < 4; e++) acc[mf][nf][e] = 0.f;

    for (int kt = 0; kt < 32; ++kt) {
        const int kb = kt*64;

        float4 ev[8];
        #pragma unroll
        for (int i = 0; i < 8; i++) {
            const int f = i*256 + tid;
            const int row = f >> 4, c4 = (f & 15)*4;
            float* ep = Ab + (size_t)row*NSEQ + kb + c4;
            float4 e = *(const float4*)ep;
            const float inv = invs[row];
            e.x *= inv; e.y *= inv; e.z *= inv; e.w *= inv;
            *(float4*)ep = e;
            ev[i] = e;
        }
        float4 vv[4];
        #pragma unroll
        for (int i = 0; i < 4; i++) {
            const int f = i*256 + tid;
            vv[i] = *(const float4*)(Vb + (size_t)(kb + (f >> 4))*DH + (f & 15)*4);
        }

        __syncthreads();

        #pragma unroll
        for (int i = 0; i < 8; i++) {
            const int f = i*256 + tid;
            const int boff = (f >> 4)*144 + (f & 15)*8;
            uint2 uh, ul;
            split_pack(ev[i], uh, ul);
            *(uint2*)(sm + PV_PH + boff) = uh;
            *(uint2*)(sm + PV_PL + boff) = ul;
        }
        #pragma unroll
        for (int i = 0; i < 4; i++) {
            const int f = i*256 + tid;
            const int boff = (f >> 4)*144 + (f & 15)*8;
            uint2 uh, ul;
            split_pack(vv[i], uh, ul);
            *(uint2*)(sm + PV_VH + boff) = uh;
            *(uint2*)(sm + PV_VL + boff) = ul;
        }
        __syncthreads();

        #pragma unroll
        for (int ks = 0; ks < 4; ks++) {
            uint32_t ah[2][4], al[2][4];
            #pragma unroll
            for (int mf = 0; mf < 2; mf++) {
                const uint32_t ao = (wq + mf*16 + l15)*144 + (ks*16 + lq*8)*2;
                ldsm4(ah[mf], smb + PV_PH + ao);
                ldsm4(al[mf], smb + PV_PL + ao);
            }
            #pragma unroll
            for (int nf = 0; nf < 4; nf++) {
                const uint32_t bo = (ks*16 + l15)*144 + (wd + nf*8)*2;
                uint32_t bhf[2], blf[2];
                ldsm2t(bhf, smb + PV_VH + bo);
                ldsm2t(blf, smb + PV_VL + bo);
                #pragma unroll
                for (int mf = 0; mf < 2; mf++) {
                    mma16816(acc[mf][nf], ah[mf], bhf);
                    mma16816(acc[mf][nf], ah[mf], blf);
                    mma16816(acc[mf][nf], al[mf], bhf);
                }
            }
        }
    }

    const int b = bh >> 3, h = bh & 7;
    #pragma unroll
    for (int mf = 0; mf < 2; mf++) {
        const int r0 = q0 + wq + mf*16 + g;
        #pragma unroll
        for (int nf = 0; nf < 4; nf++) {
            const int col = h*DH + wd + nf*8 + cq;
            float* op = g_O + (size_t)(b*NSEQ + r0)*DMODEL + col;
            *(float2*)(op)            = make_float2(acc[mf][nf][0], acc[mf][nf][1]);
            *(float2*)(op + 8*DMODEL) = make_float2(acc[mf][nf][2], acc[mf][nf][3]);
        }
    }
}

// ---------------- LayerNorm (unchanged) -----------------------------------
__global__ void __launch_bounds__(256)
ln_kernel(const float* __restrict__ gamma, const float* __restrict__ beta,
          float* __restrict__ out)
{
    const int r = blockIdx.x, tid = threadIdx.x;
    const float* y = g_Y + (size_t)r*DMODEL;
    const float a = y[tid], b = y[tid + 256];
    float s  = a + b;
    float sq = a*a + b*b;
    #pragma unroll
    for (int off = 16; off; off >>= 1) {
        s  += __shfl_xor_sync(0xffffffffu, s,  off);
        sq += __shfl_xor_sync(0xffffffffu, sq, off);
    }
    __shared__ float ws[8], wq[8];
    __shared__ float mean_s, inv_s;
    if ((tid & 31) == 0) { ws[tid >> 5] = s; wq[tid >> 5] = sq; }
    __syncthreads();
    if (tid == 0) {
        float S = 0.f, Q = 0.f;
        #pragma unroll
        for (int i = 0; i < 8; i++) { S += ws[i]; Q += wq[i]; }
        const float mean = S * (1.0f/512.0f);
        const float var  = Q * (1.0f/512.0f) - mean*mean;
        mean_s = mean;
        inv_s  = rsqrtf(var + 1e-5f);
    }
    __syncthreads();
    out[(size_t)r*DMODEL + tid]       = (a - mean_s)*inv_s*gamma[tid]       + beta[tid];
    out[(size_t)r*DMODEL + tid + 256] = (b - mean_s)*inv_s*gamma[tid + 256] + beta[tid + 256];
}

// ---------------- launch ---------------------------------------------------
extern "C" void kernel_launch(void* const* d_in, const int* in_sizes, int n_in,
                              void* d_out, int out_size)
{
    const float* x        = (const float*)d_in[0];
    const float* w_qkv    = (const float*)d_in[1];
    const float* w_unify  = (const float*)d_in[2];
    const float* b_unify  = (const float*)d_in[3];
    const float* ln_gamma = (const float*)d_in[4];
    const float* ln_beta  = (const float*)d_in[5];

    float* out_ln   = (float*)d_out;
    float* out_attn = out_ln + (size_t)ROWS*DMODEL;

    cudaFuncSetAttribute(gemm_hmma<0>, cudaFuncAttributeMaxDynamicSharedMemorySize, GM_SMEM);
    cudaFuncSetAttribute(gemm_hmma<1>, cudaFuncAttributeMaxDynamicSharedMemorySize, GM_SMEM);
    cudaFuncSetAttribute(scores_mma, cudaFuncAttributeMaxDynamicSharedMemorySize, SC_SMEM);
    cudaFuncSetAttribute(pv_mma,     cudaFuncAttributeMaxDynamicSharedMemorySize, PV_SMEM);

    // 1) QKV projection into [bh][n][dh]
    gemm_hmma<0><<<dim3(12, 64), 256, GM_SMEM>>>(x, w_qkv, nullptr, 3*DMODEL);
    // 2) E = exp(scale*QK^T + decay) -> attn (unnormalized) + partials
    scores_mma<<<dim3(16, 16, 32), 256, SC_SMEM>>>(out_attn);
    // 3) normalize attn in place + O = P @ V
    pv_mma<<<dim3(16, 32), 256, PV_SMEM>>>(out_attn);
    // 4) unify GEMM + bias
    gemm_hmma<1><<<dim3(4, 64), 256, GM_SMEM>>>(nullptr, w_unify, b_unify, DMODEL);
    // 5) LayerNorm -> first output
    ln_kernel<<<ROWS, 256>>>(ln_gamma, ln_beta, out_ln);
}

// round 7
// speedup vs baseline: 3.5674x; 1.0370x over previous
#include <cuda_runtime.h>
#include <cuda_bf16.h>
#include <cstdint>
#include <math.h>

#define HEADS   8
#define DH      64
#define NSEQ    2048
#define BATCH   4
#define DMODEL  512
#define ROWS    (BATCH*NSEQ)    // 8192
#define BHN     (BATCH*HEADS)   // 32

// ---------------- scratch (device globals; no allocations) ----------------
__device__ float g_Q[(size_t)BHN*NSEQ*DH];
__device__ float g_K[(size_t)BHN*NSEQ*DH];
__device__ float g_V[(size_t)BHN*NSEQ*DH];
__device__ float g_O[(size_t)ROWS*DMODEL];
__device__ float g_Y[(size_t)ROWS*DMODEL];

// ================= warp-level tensor core helpers (sm_80+ ISA) =============
__device__ __forceinline__ uint32_t smem_u32(const void* p) {
    uint32_t a;
    asm("{ .reg .u64 t; cvta.to.shared.u64 t, %1; cvt.u32.u64 %0, t; }"
        : "=r"(a) : "l"(p));
    return a;
}
__device__ __forceinline__ void ldsm4(uint32_t* r, uint32_t a) {
    asm volatile("ldmatrix.sync.aligned.m8n8.x4.shared.b16 {%0,%1,%2,%3}, [%4];"
        : "=r"(r[0]), "=r"(r[1]), "=r"(r[2]), "=r"(r[3]) : "r"(a));
}
__device__ __forceinline__ void ldsm2(uint32_t* r, uint32_t a) {
    asm volatile("ldmatrix.sync.aligned.m8n8.x2.shared.b16 {%0,%1}, [%2];"
        : "=r"(r[0]), "=r"(r[1]) : "r"(a));
}
__device__ __forceinline__ void ldsm2t(uint32_t* r, uint32_t a) {
    asm volatile("ldmatrix.sync.aligned.m8n8.x2.trans.shared.b16 {%0,%1}, [%2];"
        : "=r"(r[0]), "=r"(r[1]) : "r"(a));
}
__device__ __forceinline__ void mma16816(float* d, const uint32_t* a, const uint32_t* b) {
    asm volatile("mma.sync.aligned.m16n8k16.row.col.f32.bf16.bf16.f32 "
        "{%0,%1,%2,%3}, {%4,%5,%6,%7}, {%8,%9}, {%0,%1,%2,%3};"
        : "+f"(d[0]), "+f"(d[1]), "+f"(d[2]), "+f"(d[3])
        : "r"(a[0]), "r"(a[1]), "r"(a[2]), "r"(a[3]), "r"(b[0]), "r"(b[1]));
}

// split fp32 -> (hi, lo) bf16, packed as 2x uint32 (4 elems)
__device__ __forceinline__ void split_pack(float4 f, uint2& uh, uint2& ul) {
    __nv_bfloat16 h0 = __float2bfloat16(f.x), h1 = __float2bfloat16(f.y),
                  h2 = __float2bfloat16(f.z), h3 = __float2bfloat16(f.w);
    __nv_bfloat16 l0 = __float2bfloat16(f.x - __bfloat162float(h0));
    __nv_bfloat16 l1 = __float2bfloat16(f.y - __bfloat162float(h1));
    __nv_bfloat16 l2 = __float2bfloat16(f.z - __bfloat162float(h2));
    __nv_bfloat16 l3 = __float2bfloat16(f.w - __bfloat162float(h3));
    uh.x = (uint32_t)__bfloat16_as_ushort(h0) | ((uint32_t)__bfloat16_as_ushort(h1) << 16);
    uh.y = (uint32_t)__bfloat16_as_ushort(h2) | ((uint32_t)__bfloat16_as_ushort(h3) << 16);
    ul.x = (uint32_t)__bfloat16_as_ushort(l0) | ((uint32_t)__bfloat16_as_ushort(l1) << 16);
    ul.y = (uint32_t)__bfloat16_as_ushort(l2) | ((uint32_t)__bfloat16_as_ushort(l3) << 16);
}
// split-pack two scalars
__device__ __forceinline__ void pack2(float x, float y, uint32_t& h, uint32_t& l) {
    __nv_bfloat16 hx = __float2bfloat16(x), hy = __float2bfloat16(y);
    __nv_bfloat16 lx = __float2bfloat16(x - __bfloat162float(hx));
    __nv_bfloat16 ly = __float2bfloat16(y - __bfloat162float(hy));
    h = (uint32_t)__bfloat16_as_ushort(hx) | ((uint32_t)__bfloat16_as_ushort(hy) << 16);
    l = (uint32_t)__bfloat16_as_ushort(lx) | ((uint32_t)__bfloat16_as_ushort(ly) << 16);
}

// ======== HMMA projection GEMM (unchanged, verified) =======================
#define GM_AH   0
#define GM_AL   18432
#define GM_BH   36864
#define GM_BL   54272
#define GM_SMEM 71680

template<int MODE>
__global__ void __launch_bounds__(256)
gemm_hmma(const float* __restrict__ A_in, const float* __restrict__ B,
          const float* __restrict__ bias, int ldb)
{
    extern __shared__ char sm[];
    const uint32_t smb = smem_u32(sm);
    const float* A = (MODE == 0) ? A_in : g_O;

    const int bm = blockIdx.y * 128;
    const int bn = blockIdx.x * 128;
    const int tid = threadIdx.x;
    const int wid = tid >> 5, lane = tid & 31;

    const int wq = (wid & 3)*32, nw = (wid >> 2)*64;
    const int l15 = lane & 15;
    const int lq = lane >> 4;
    const int g = lane >> 2, cq = (lane & 3)*2;

    float acc[2][8][4];
    #pragma unroll
    for (int mf = 0; mf < 2; mf++)
        #pragma unroll
        for (int nf = 0; nf < 8; nf++)
            #pragma unroll
            for (int e = 0; e < 4; e++) acc[mf][nf][e] = 0.f;

    for (int ks0 = 0; ks0 < 8; ++ks0) {
        const int k0 = ks0*64;
        float4 av[8], bv[8];
        #pragma unroll
        for (int i = 0; i < 8; i++) {
            const int f = i*256 + tid;
            av[i] = *(const float4*)(A + (size_t)(bm + (f >> 4))*512 + k0 + (f & 15)*4);
        }
        #pragma unroll
        for (int i = 0; i < 8; i++) {
            const int f = i*256 + tid;
            bv[i] = *(const float4*)(B + (size_t)(k0 + (f >> 5))*ldb + bn + (f & 31)*4);
        }
        __syncthreads();
        #pragma unroll
        for (int i = 0; i < 8; i++) {
            const int f = i*256 + tid;
            const int boff = (f >> 4)*144 + (f & 15)*8;
            uint2 uh, ul;
            split_pack(av[i], uh, ul);
            *(uint2*)(sm + GM_AH + boff) = uh;
            *(uint2*)(sm + GM_AL + boff) = ul;
        }
        #pragma unroll
        for (int i = 0; i < 8; i++) {
            const int f = i*256 + tid;
            const int boff = (f >> 5)*272 + (f & 31)*8;
            uint2 uh, ul;
            split_pack(bv[i], uh, ul);
            *(uint2*)(sm + GM_BH + boff) = uh;
            *(uint2*)(sm + GM_BL + boff) = ul;
        }
        __syncthreads();

        #pragma unroll
        for (int ks = 0; ks < 4; ks++) {
            uint32_t ah[2][4], al[2][4];
            #pragma unroll
            for (int mf = 0; mf < 2; mf++) {
                const uint32_t ao = (wq + mf*16 + l15)*144 + (ks*16 + lq*8)*2;
                ldsm4(ah[mf], smb + GM_AH + ao);
                ldsm4(al[mf], smb + GM_AL + ao);
            }
            #pragma unroll
            for (int nf = 0; nf < 8; nf++) {
                const uint32_t bo = (ks*16 + l15)*272 + (nw + nf*8)*2;
                uint32_t bhf[2], blf[2];
                ldsm2t(bhf, smb + GM_BH + bo);
                ldsm2t(blf, smb + GM_BL + bo);
                #pragma unroll
                for (int mf = 0; mf < 2; mf++) {
                    mma16816(acc[mf][nf], ah[mf], bhf);
                    mma16816(acc[mf][nf], ah[mf], blf);
                    mma16816(acc[mf][nf], al[mf], bhf);
                }
            }
        }
    }

    if (MODE == 0) {
        const int which = bn >> 9;
        float* dst = (which == 0) ? g_Q : (which == 1) ? g_K : g_V;
        const int cbase = bn & 511;
        #pragma unroll
        for (int mf = 0; mf < 2; mf++) {
            const int r = bm + wq + mf*16 + g;
            const int bidx = r >> 11, nidx = r & (NSEQ-1);
            #pragma unroll
            for (int nf = 0; nf < 8; nf++) {
                const int cb = cbase + nw + nf*8 + cq;
                const int h = cb >> 6, dd = cb & 63;
                float* p = dst + (((size_t)bidx*HEADS + h)*NSEQ + nidx)*DH + dd;
                *(float2*)(p)        = make_float2(acc[mf][nf][0], acc[mf][nf][1]);
                *(float2*)(p + 8*DH) = make_float2(acc[mf][nf][2], acc[mf][nf][3]);
            }
        }
    } else {
        #pragma unroll
        for (int mf = 0; mf < 2; mf++) {
            const int r = bm + wq + mf*16 + g;
            #pragma unroll
            for (int nf = 0; nf < 8; nf++) {
                const int col = bn + nw + nf*8 + cq;
                const float b0 = bias[col], b1 = bias[col + 1];
                float* yr = g_Y + (size_t)r*DMODEL + col;
                *(float2*)(yr)            = make_float2(acc[mf][nf][0] + b0,
                                                        acc[mf][nf][1] + b1);
                *(float2*)(yr + 8*DMODEL) = make_float2(acc[mf][nf][2] + b0,
                                                        acc[mf][nf][3] + b1);
            }
        }
    }
}

// ============== fused attention: scores + PV + attn write ==================
// block = (qt, bh). Pass 1: per 128-key tile compute E fragments, accumulate
// rowsums + unnormalized O via register C->A repack. Then scale+write O.
// Pass 2: recompute E (bitwise identical), multiply by inv, write attn.
#define AF_QH   0
#define AF_QL   18432
#define AF_KH   36864
#define AF_KL   55296
#define AF_VH   73728
#define AF_VL   92160
#define AF_INV  110592
#define AF_PS   111104
#define AF_SMEM 112128

__global__ void __launch_bounds__(256, 1)
attn_fused(float* __restrict__ attn)
{
    extern __shared__ char sm[];
    const uint32_t smb = smem_u32(sm);
    const int tid = threadIdx.x;
    const int wid = tid >> 5, lane = tid & 31;
    const int q0 = blockIdx.x * 128;
    const int bh = blockIdx.y;

    const int mw = (wid & 3)*32, nw = (wid >> 2)*64;
    const int l15 = lane & 15, l7 = lane & 7;
    const int lh = (lane >> 3) & 1, lq = lane >> 4;
    const int g = lane >> 2, cq = (lane & 3)*2;

    // ---- stage Q (persistent across both passes) ----
    const float* Qb = g_Q + ((size_t)bh*NSEQ + q0)*DH;
    #pragma unroll
    for (int i = 0; i < 8; i++) {
        const int f = i*256 + tid;
        const int boff = (f >> 4)*144 + (f & 15)*8;
        uint2 uh, ul;
        split_pack(*(const float4*)(Qb + (size_t)(f >> 4)*DH + (f & 15)*4), uh, ul);
        *(uint2*)(sm + AF_QH + boff) = uh;
        *(uint2*)(sm + AF_QL + boff) = ul;
    }

    const float* Kb = g_K + (size_t)bh*NSEQ*DH;
    const float* Vb = g_V + (size_t)bh*NSEQ*DH;

    float acc_o[2][8][4];
    #pragma unroll
    for (int mf = 0; mf < 2; mf++)
        #pragma unroll
        for (int nf = 0; nf < 8; nf++)
            #pragma unroll
            for (int e = 0; e < 4; e++) acc_o[mf][nf][e] = 0.f;
    float psum[2][2] = {{0.f, 0.f}, {0.f, 0.f}};

    // =================== pass 1: rowsums + unnormalized O ==================
    for (int kt = 0; kt < 16; ++kt) {
        const int kb = kt*128;
        float4 kv4[8], vv4[8];
        #pragma unroll
        for (int i = 0; i < 8; i++) {
            const int f = i*256 + tid;
            kv4[i] = *(const float4*)(Kb + (size_t)(kb + (f >> 4))*DH + (f & 15)*4);
            vv4[i] = *(const float4*)(Vb + (size_t)(kb + (f >> 4))*DH + (f & 15)*4);
        }
        __syncthreads();   // prior iteration's ldsm reads done (or Q stage)
        #pragma unroll
        for (int i = 0; i < 8; i++) {
            const int f = i*256 + tid;
            const int boff = (f >> 4)*144 + (f & 15)*8;
            uint2 uh, ul;
            split_pack(kv4[i], uh, ul);
            *(uint2*)(sm + AF_KH + boff) = uh;
            *(uint2*)(sm + AF_KL + boff) = ul;
            split_pack(vv4[i], uh, ul);
            *(uint2*)(sm + AF_VH + boff) = uh;
            *(uint2*)(sm + AF_VL + boff) = ul;
        }
        __syncthreads();

        // S = Q K^T (split bf16, 3 products)
        float acc_s[2][8][4];
        #pragma unroll
        for (int mf = 0; mf < 2; mf++)
            #pragma unroll
            for (int nf = 0; nf < 8; nf++)
                #pragma unroll
                for (int e = 0; e < 4; e++) acc_s[mf][nf][e] = 0.f;
        #pragma unroll
        for (int ks = 0; ks < 4; ks++) {
            uint32_t ah[2][4], al[2][4];
            #pragma unroll
            for (int mf = 0; mf < 2; mf++) {
                const uint32_t ao = (mw + mf*16 + l15)*144 + (ks*16 + lq*8)*2;
                ldsm4(ah[mf], smb + AF_QH + ao);
                ldsm4(al[mf], smb + AF_QL + ao);
            }
            #pragma unroll
            for (int nf = 0; nf < 8; nf++) {
                const uint32_t bo = (nw + nf*8 + l7)*144 + (ks*16 + lh*8)*2;
                uint32_t bhf[2], blf[2];
                ldsm2(bhf, smb + AF_KH + bo);
                ldsm2(blf, smb + AF_KL + bo);
                #pragma unroll
                for (int mf = 0; mf < 2; mf++) {
                    mma16816(acc_s[mf][nf], ah[mf], bhf);
                    mma16816(acc_s[mf][nf], ah[mf], blf);
                    mma16816(acc_s[mf][nf], al[mf], bhf);
                }
            }
        }

        // exp + rowsum + pack E as bf16 hi/lo A-fragments (registers only)
        uint32_t eh[2][8][2], el[2][8][2];
        #pragma unroll
        for (int nf = 0; nf < 8; nf++) {
            const int c = nw + nf*8 + cq;
            const float dec0 = __expf((float)(kb + c)     * -0.02f);
            const float dec1 = __expf((float)(kb + c + 1) * -0.02f);
            #pragma unroll
            for (int mf = 0; mf < 2; mf++) {
                const float e0 = __expf(fmaf(acc_s[mf][nf][0], 0.125f, dec0));
                const float e1 = __expf(fmaf(acc_s[mf][nf][1], 0.125f, dec1));
                const float e2 = __expf(fmaf(acc_s[mf][nf][2], 0.125f, dec0));
                const float e3 = __expf(fmaf(acc_s[mf][nf][3], 0.125f, dec1));
                psum[mf][0] += e0 + e1;
                psum[mf][1] += e2 + e3;
                pack2(e0, e1, eh[mf][nf][0], el[mf][nf][0]);
                pack2(e2, e3, eh[mf][nf][1], el[mf][nf][1]);
            }
        }

        // PV: O += E @ V over this warp's k-halfrange (register A fragments)
        #pragma unroll
        for (int ks2 = 0; ks2 < 4; ks2++) {
            uint32_t pah[2][4], pal[2][4];
            #pragma unroll
            for (int mf = 0; mf < 2; mf++) {
                pah[mf][0] = eh[mf][2*ks2][0];   pal[mf][0] = el[mf][2*ks2][0];
                pah[mf][1] = eh[mf][2*ks2][1];   pal[mf][1] = el[mf][2*ks2][1];
                pah[mf][2] = eh[mf][2*ks2+1][0]; pal[mf][2] = el[mf][2*ks2+1][0];
                pah[mf][3] = eh[mf][2*ks2+1][1]; pal[mf][3] = el[mf][2*ks2+1][1];
            }
            #pragma unroll
            for (int nf = 0; nf < 8; nf++) {     // d groups of 8
                const uint32_t bo = (nw + ks2*16 + l15)*144 + (nf*8)*2;
                uint32_t bhf[2], blf[2];
                ldsm2t(bhf, smb + AF_VH + bo);
                ldsm2t(blf, smb + AF_VL + bo);
                #pragma unroll
                for (int mf = 0; mf < 2; mf++) {
                    mma16816(acc_o[mf][nf], pah[mf], bhf);
                    mma16816(acc_o[mf][nf], pah[mf], blf);
                    mma16816(acc_o[mf][nf], pal[mf], bhf);
                }
            }
        }
    }

    // ---- rowsums -> invs ----
    #pragma unroll
    for (int off = 1; off < 4; off <<= 1) {
        psum[0][0] += __shfl_xor_sync(0xffffffffu, psum[0][0], off);
        psum[0][1] += __shfl_xor_sync(0xffffffffu, psum[0][1], off);
        psum[1][0] += __shfl_xor_sync(0xffffffffu, psum[1][0], off);
        psum[1][1] += __shfl_xor_sync(0xffffffffu, psum[1][1], off);
    }
    __syncthreads();                     // all pass-1 ldsm reads done
    float* ps   = (float*)(sm + AF_PS);
    float* invs = (float*)(sm + AF_INV);
    if ((lane & 3) == 0) {
        #pragma unroll
        for (int mf = 0; mf < 2; mf++)
            #pragma unroll
            for (int h = 0; h < 2; h++)
                ps[wid*32 + mf*16 + h*8 + g] = psum[mf][h];
    }
    __syncthreads();
    if (tid < 128) invs[tid] = 1.0f / (ps[tid] + ps[tid + 128]);
    __syncthreads();

    // ---- scale O by inv, reduce warp pairs via smem, write g_O ----
    #pragma unroll
    for (int mf = 0; mf < 2; mf++) {
        const float inv0 = invs[mw + mf*16 + g];
        const float inv1 = invs[mw + mf*16 + 8 + g];
        #pragma unroll
        for (int nf = 0; nf < 8; nf++) {
            acc_o[mf][nf][0] *= inv0; acc_o[mf][nf][1] *= inv0;
            acc_o[mf][nf][2] *= inv1; acc_o[mf][nf][3] *= inv1;
        }
    }
    float* exch = (float*)(sm + AF_KH);  // 32KB scratch (K buffers dead)
    if (wid >= 4) {
        #pragma unroll
        for (int mf = 0; mf < 2; mf++)
            #pragma unroll
            for (int nf = 0; nf < 8; nf++) {
                float* e0 = exch + (wid & 3)*2048 + (mf*16 + g)*64 + nf*8 + cq;
                *(float2*)(e0)       = make_float2(acc_o[mf][nf][0], acc_o[mf][nf][1]);
                *(float2*)(e0 + 512) = make_float2(acc_o[mf][nf][2], acc_o[mf][nf][3]); // +8 rows
            }
    }
    __syncthreads();
    if (wid < 4) {
        const int b = bh >> 3, h = bh & 7;
        #pragma unroll
        for (int mf = 0; mf < 2; mf++) {
            const int r0 = q0 + mw + mf*16 + g;
            #pragma unroll
            for (int nf = 0; nf < 8; nf++) {
                const float* e0 = exch + wid*2048 + (mf*16 + g)*64 + nf*8 + cq;
                const float2 p0 = *(const float2*)(e0);
                const float2 p1 = *(const float2*)(e0 + 512);
                float* op = g_O + (size_t)(b*NSEQ + r0)*DMODEL + h*DH + nf*8 + cq;
                *(float2*)(op)            = make_float2(acc_o[0+mf][nf][0] + p0.x,
                                                        acc_o[mf][nf][1] + p0.y);
                *(float2*)(op + 8*DMODEL) = make_float2(acc_o[mf][nf][2] + p1.x,
                                                        acc_o[mf][nf][3] + p1.y);
            }
        }
    }
    __syncthreads();                     // exch reads done before K restage

    // =================== pass 2: recompute E, write attn ===================
    for (int kt = 0; kt < 16; ++kt) {
        const int kb = kt*128;
        float4 kv4[8];
        #pragma unroll
        for (int i = 0; i < 8; i++) {
            const int f = i*256 + tid;
            kv4[i] = *(const float4*)(Kb + (size_t)(kb + (f >> 4))*DH + (f & 15)*4);
        }
        __syncthreads();
        #pragma unroll
        for (int i = 0; i < 8; i++) {
            const int f = i*256 + tid;
            const int boff = (f >> 4)*144 + (f & 15)*8;
            uint2 uh, ul;
            split_pack(kv4[i], uh, ul);
            *(uint2*)(sm + AF_KH + boff) = uh;
            *(uint2*)(sm + AF_KL + boff) = ul;
        }
        __syncthreads();

        float acc_s[2][8][4];
        #pragma unroll
        for (int mf = 0; mf < 2; mf++)
            #pragma unroll
            for (int nf = 0; nf < 8; nf++)
                #pragma unroll
                for (int e = 0; e < 4; e++) acc_s[mf][nf][e] = 0.f;
        #pragma unroll
        for (int ks = 0; ks < 4; ks++) {
            uint32_t ah[2][4], al[2][4];
            #pragma unroll
            for (int mf = 0; mf < 2; mf++) {
                const uint32_t ao = (mw + mf*16 + l15)*144 + (ks*16 + lq*8)*2;
                ldsm4(ah[mf], smb + AF_QH + ao);
                ldsm4(al[mf], smb + AF_QL + ao);
            }
            #pragma unroll
            for (int nf = 0; nf < 8; nf++) {
                const uint32_t bo = (nw + nf*8 + l7)*144 + (ks*16 + lh*8)*2;
                uint32_t bhf[2], blf[2];
                ldsm2(bhf, smb + AF_KH + bo);
                ldsm2(blf, smb + AF_KL + bo);
                #pragma unroll
                for (int mf = 0; mf < 2; mf++) {
                    mma16816(acc_s[mf][nf], ah[mf], bhf);
                    mma16816(acc_s[mf][nf], ah[mf], blf);
                    mma16816(acc_s[mf][nf], al[mf], bhf);
                }
            }
        }

        #pragma unroll
        for (int mf = 0; mf < 2; mf++) {
            const float inv0 = invs[mw + mf*16 + g];
            const float inv1 = invs[mw + mf*16 + 8 + g];
            const int r0 = q0 + mw + mf*16 + g;
            #pragma unroll
            for (int nf = 0; nf < 8; nf++) {
                const int c = nw + nf*8 + cq;
                const float dec0 = __expf((float)(kb + c)     * -0.02f);
                const float dec1 = __expf((float)(kb + c + 1) * -0.02f);
                const float e0 = __expf(fmaf(acc_s[mf][nf][0], 0.125f, dec0)) * inv0;
                const float e1 = __expf(fmaf(acc_s[mf][nf][1], 0.125f, dec1)) * inv0;
                const float e2 = __expf(fmaf(acc_s[mf][nf][2], 0.125f, dec0)) * inv1;
                const float e3 = __expf(fmaf(acc_s[mf][nf][3], 0.125f, dec1)) * inv1;
                float* p = attn + ((size_t)bh*NSEQ + r0)*NSEQ + kb + c;
                *(float2*)(p)          = make_float2(e0, e1);
                *(float2*)(p + 8*NSEQ) = make_float2(e2, e3);
            }
        }
    }
}

// ---------------- LayerNorm (unchanged) -----------------------------------
__global__ void __launch_bounds__(256)
ln_kernel(const float* __restrict__ gamma, const float* __restrict__ beta,
          float* __restrict__ out)
{
    const int r = blockIdx.x, tid = threadIdx.x;
    const float* y = g_Y + (size_t)r*DMODEL;
    const float a = y[tid], b = y[tid + 256];
    float s  = a + b;
    float sq = a*a + b*b;
    #pragma unroll
    for (int off = 16; off; off >>= 1) {
        s  += __shfl_xor_sync(0xffffffffu, s,  off);
        sq += __shfl_xor_sync(0xffffffffu, sq, off);
    }
    __shared__ float ws[8], wq[8];
    __shared__ float mean_s, inv_s;
    if ((tid & 31) == 0) { ws[tid >> 5] = s; wq[tid >> 5] = sq; }
    __syncthreads();
    if (tid == 0) {
        float S = 0.f, Q = 0.f;
        #pragma unroll
        for (int i = 0; i < 8; i++) { S += ws[i]; Q += wq[i]; }
        const float mean = S * (1.0f/512.0f);
        const float var  = Q * (1.0f/512.0f) - mean*mean;
        mean_s = mean;
        inv_s  = rsqrtf(var + 1e-5f);
    }
    __syncthreads();
    out[(size_t)r*DMODEL + tid]       = (a - mean_s)*inv_s*gamma[tid]       + beta[tid];
    out[(size_t)r*DMODEL + tid + 256] = (b - mean_s)*inv_s*gamma[tid + 256] + beta[tid + 256];
}

// ---------------- launch ---------------------------------------------------
extern "C" void kernel_launch(void* const* d_in, const int* in_sizes, int n_in,
                              void* d_out, int out_size)
{
    const float* x        = (const float*)d_in[0];
    const float* w_qkv    = (const float*)d_in[1];
    const float* w_unify  = (const float*)d_in[2];
    const float* b_unify  = (const float*)d_in[3];
    const float* ln_gamma = (const float*)d_in[4];
    const float* ln_beta  = (const float*)d_in[5];

    float* out_ln   = (float*)d_out;
    float* out_attn = out_ln + (size_t)ROWS*DMODEL;

    cudaFuncSetAttribute(gemm_hmma<0>, cudaFuncAttributeMaxDynamicSharedMemorySize, GM_SMEM);
    cudaFuncSetAttribute(gemm_hmma<1>, cudaFuncAttributeMaxDynamicSharedMemorySize, GM_SMEM);
    cudaFuncSetAttribute(attn_fused,   cudaFuncAttributeMaxDynamicSharedMemorySize, AF_SMEM);

    // 1) QKV projection into [bh][n][dh]
    gemm_hmma<0><<<dim3(12, 64), 256, GM_SMEM>>>(x, w_qkv, nullptr, 3*DMODEL);
    // 2) fused attention: O (unnormalized-then-scaled) + normalized attn write
    attn_fused<<<dim3(16, 32), 256, AF_SMEM>>>(out_attn);
    // 3) unify GEMM + bias
    gemm_hmma<1><<<dim3(4, 64), 256, GM_SMEM>>>(nullptr, w_unify, b_unify, DMODEL);
    // 4) LayerNorm -> first output
    ln_kernel<<<ROWS, 256>>>(ln_gamma, ln_beta, out_ln);
}

// round 8
// speedup vs baseline: 4.8121x; 1.3489x over previous
#include <cuda_runtime.h>
#include <cuda_fp16.h>
#include <cstdint>
#include <math.h>

#define HEADS   8
#define DH      64
#define NSEQ    2048
#define BATCH   4
#define DMODEL  512
#define ROWS    (BATCH*NSEQ)    // 8192
#define BHN     (BATCH*HEADS)   // 32

// ---------------- scratch (device globals; no allocations) ----------------
__device__ float g_Q[(size_t)BHN*NSEQ*DH];
__device__ float g_K[(size_t)BHN*NSEQ*DH];
__device__ float g_V[(size_t)BHN*NSEQ*DH];
__device__ float g_O[(size_t)ROWS*DMODEL];
__device__ float g_Y[(size_t)ROWS*DMODEL];

// ================= warp-level tensor core helpers (sm_80+ ISA) =============
__device__ __forceinline__ uint32_t smem_u32(const void* p) {
    uint32_t a;
    asm("{ .reg .u64 t; cvta.to.shared.u64 t, %1; cvt.u32.u64 %0, t; }"
        : "=r"(a) : "l"(p));
    return a;
}
__device__ __forceinline__ void ldsm4(uint32_t* r, uint32_t a) {
    asm volatile("ldmatrix.sync.aligned.m8n8.x4.shared.b16 {%0,%1,%2,%3}, [%4];"
        : "=r"(r[0]), "=r"(r[1]), "=r"(r[2]), "=r"(r[3]) : "r"(a));
}
__device__ __forceinline__ void ldsm2(uint32_t* r, uint32_t a) {
    asm volatile("ldmatrix.sync.aligned.m8n8.x2.shared.b16 {%0,%1}, [%2];"
        : "=r"(r[0]), "=r"(r[1]) : "r"(a));
}
__device__ __forceinline__ void ldsm2t(uint32_t* r, uint32_t a) {
    asm volatile("ldmatrix.sync.aligned.m8n8.x2.trans.shared.b16 {%0,%1}, [%2];"
        : "=r"(r[0]), "=r"(r[1]) : "r"(a));
}
// fp16 inputs, fp32 accumulate
__device__ __forceinline__ void mma16816(float* d, const uint32_t* a, const uint32_t* b) {
    asm volatile("mma.sync.aligned.m16n8k16.row.col.f32.f16.f16.f32 "
        "{%0,%1,%2,%3}, {%4,%5,%6,%7}, {%8,%9}, {%0,%1,%2,%3};"
        : "+f"(d[0]), "+f"(d[1]), "+f"(d[2]), "+f"(d[3])
        : "r"(a[0]), "r"(a[1]), "r"(a[2]), "r"(a[3]), "r"(b[0]), "r"(b[1]));
}

// split fp32 -> (hi, lo) fp16, packed as 2x uint32 (4 elems)
__device__ __forceinline__ void split_pack_h(float4 f, uint2& uh, uint2& ul) {
    __half h0 = __float2half_rn(f.x), h1 = __float2half_rn(f.y),
           h2 = __float2half_rn(f.z), h3 = __float2half_rn(f.w);
    __half l0 = __float2half_rn(f.x - __half2float(h0));
    __half l1 = __float2half_rn(f.y - __half2float(h1));
    __half l2 = __float2half_rn(f.z - __half2float(h2));
    __half l3 = __float2half_rn(f.w - __half2float(h3));
    uh.x = (uint32_t)__half_as_ushort(h0) | ((uint32_t)__half_as_ushort(h1) << 16);
    uh.y = (uint32_t)__half_as_ushort(h2) | ((uint32_t)__half_as_ushort(h3) << 16);
    ul.x = (uint32_t)__half_as_ushort(l0) | ((uint32_t)__half_as_ushort(l1) << 16);
    ul.y = (uint32_t)__half_as_ushort(l2) | ((uint32_t)__half_as_ushort(l3) << 16);
}
// hi-only pack (A-side operands)
__device__ __forceinline__ uint2 pack_hi4(float4 f) {
    uint2 u;
    u.x = (uint32_t)__half_as_ushort(__float2half_rn(f.x)) |
          ((uint32_t)__half_as_ushort(__float2half_rn(f.y)) << 16);
    u.y = (uint32_t)__half_as_ushort(__float2half_rn(f.z)) |
          ((uint32_t)__half_as_ushort(__float2half_rn(f.w)) << 16);
    return u;
}
__device__ __forceinline__ uint32_t pack2hi(float x, float y) {
    return (uint32_t)__half_as_ushort(__float2half_rn(x)) |
           ((uint32_t)__half_as_ushort(__float2half_rn(y)) << 16);
}

// ======== HMMA projection GEMM: A hi-only, B hi+lo, 2-product ==============
// MODE 0: A = x, B = w_qkv (ldb=1536) -> scatter g_Q/g_K/g_V
// MODE 1: A = g_O, B = w_unify (ldb=512) -> + bias -> g_Y
// smem: Ah [128][72] f16 (144 B rows), Bh/Bl [64][136] f16 (272 B rows)
#define GM_AH   0
#define GM_BH   18432
#define GM_BL   35840
#define GM_SMEM 53248

template<int MODE>
__global__ void __launch_bounds__(256, 2)
gemm_hmma(const float* __restrict__ A_in, const float* __restrict__ B,
          const float* __restrict__ bias, int ldb)
{
    extern __shared__ char sm[];
    const uint32_t smb = smem_u32(sm);
    const float* A = (MODE == 0) ? A_in : g_O;

    const int bm = blockIdx.y * 128;
    const int bn = blockIdx.x * 128;
    const int tid = threadIdx.x;
    const int wid = tid >> 5, lane = tid & 31;

    const int wq = (wid & 3)*32, nw = (wid >> 2)*64;
    const int l15 = lane & 15;
    const int lq = lane >> 4;
    const int g = lane >> 2, cq = (lane & 3)*2;

    float acc[2][8][4];
    #pragma unroll
    for (int mf = 0; mf < 2; mf++)
        #pragma unroll
        for (int nf = 0; nf < 8; nf++)
            #pragma unroll
            for (int e = 0; e < 4; e++) acc[mf][nf][e] = 0.f;

    for (int ks0 = 0; ks0 < 8; ++ks0) {
        const int k0 = ks0*64;
        __syncthreads();               // prior MMAs done reading smem
        #pragma unroll
        for (int i = 0; i < 8; i++) {  // A slab 128x64: hi only
            const int f = i*256 + tid;
            float4 a = *(const float4*)(A + (size_t)(bm + (f >> 4))*512 + k0 + (f & 15)*4);
            *(uint2*)(sm + GM_AH + (f >> 4)*144 + (f & 15)*8) = pack_hi4(a);
        }
        #pragma unroll
        for (int i = 0; i < 8; i++) {  // B slab 64x128: hi+lo
            const int f = i*256 + tid;
            float4 b = *(const float4*)(B + (size_t)(k0 + (f >> 5))*ldb + bn + (f & 31)*4);
            uint2 uh, ul;
            split_pack_h(b, uh, ul);
            const int boff = (f >> 5)*272 + (f & 31)*8;
            *(uint2*)(sm + GM_BH + boff) = uh;
            *(uint2*)(sm + GM_BL + boff) = ul;
        }
        __syncthreads();

        #pragma unroll
        for (int ks = 0; ks < 4; ks++) {
            uint32_t ah[2][4];
            #pragma unroll
            for (int mf = 0; mf < 2; mf++)
                ldsm4(ah[mf], smb + GM_AH + (wq + mf*16 + l15)*144 + (ks*16 + lq*8)*2);
            #pragma unroll
            for (int nf = 0; nf < 8; nf++) {
                const uint32_t bo = (ks*16 + l15)*272 + (nw + nf*8)*2;
                uint32_t bhf[2], blf[2];
                ldsm2t(bhf, smb + GM_BH + bo);
                ldsm2t(blf, smb + GM_BL + bo);
                #pragma unroll
                for (int mf = 0; mf < 2; mf++) {
                    mma16816(acc[mf][nf], ah[mf], bhf);
                    mma16816(acc[mf][nf], ah[mf], blf);
                }
            }
        }
    }

    if (MODE == 0) {
        const int which = bn >> 9;
        float* dst = (which == 0) ? g_Q : (which == 1) ? g_K : g_V;
        const int cbase = bn & 511;
        #pragma unroll
        for (int mf = 0; mf < 2; mf++) {
            const int r = bm + wq + mf*16 + g;
            const int bidx = r >> 11, nidx = r & (NSEQ-1);
            #pragma unroll
            for (int nf = 0; nf < 8; nf++) {
                const int cb = cbase + nw + nf*8 + cq;
                const int h = cb >> 6, dd = cb & 63;
                float* p = dst + (((size_t)bidx*HEADS + h)*NSEQ + nidx)*DH + dd;
                *(float2*)(p)        = make_float2(acc[mf][nf][0], acc[mf][nf][1]);
                *(float2*)(p + 8*DH) = make_float2(acc[mf][nf][2], acc[mf][nf][3]);
            }
        }
    } else {
        #pragma unroll
        for (int mf = 0; mf < 2; mf++) {
            const int r = bm + wq + mf*16 + g;
            #pragma unroll
            for (int nf = 0; nf < 8; nf++) {
                const int col = bn + nw + nf*8 + cq;
                const float b0 = bias[col], b1 = bias[col + 1];
                float* yr = g_Y + (size_t)r*DMODEL + col;
                *(float2*)(yr)            = make_float2(acc[mf][nf][0] + b0,
                                                        acc[mf][nf][1] + b1);
                *(float2*)(yr + 8*DMODEL) = make_float2(acc[mf][nf][2] + b0,
                                                        acc[mf][nf][3] + b1);
            }
        }
    }
}

// ============== fused attention: scores + PV + attn write ==================
// Q hi-only (A side); K,V hi+lo (B side); E hi-only (A side of PV).
#define AF_QH   0
#define AF_KH   18432
#define AF_KL   36864
#define AF_VH   55296
#define AF_VL   73728
#define AF_INV  92160
#define AF_PS   92672
#define AF_SMEM 93696

__global__ void __launch_bounds__(256, 1)
attn_fused(float* __restrict__ attn)
{
    extern __shared__ char sm[];
    const uint32_t smb = smem_u32(sm);
    const int tid = threadIdx.x;
    const int wid = tid >> 5, lane = tid & 31;
    const int q0 = blockIdx.x * 128;
    const int bh = blockIdx.y;

    const int mw = (wid & 3)*32, nw = (wid >> 2)*64;
    const int l15 = lane & 15, l7 = lane & 7;
    const int lh = (lane >> 3) & 1, lq = lane >> 4;
    const int g = lane >> 2, cq = (lane & 3)*2;

    // ---- stage Q hi (persistent across both passes) ----
    const float* Qb = g_Q + ((size_t)bh*NSEQ + q0)*DH;
    #pragma unroll
    for (int i = 0; i < 8; i++) {
        const int f = i*256 + tid;
        float4 q = *(const float4*)(Qb + (size_t)(f >> 4)*DH + (f & 15)*4);
        *(uint2*)(sm + AF_QH + (f >> 4)*144 + (f & 15)*8) = pack_hi4(q);
    }

    const float* Kb = g_K + (size_t)bh*NSEQ*DH;
    const float* Vb = g_V + (size_t)bh*NSEQ*DH;

    float acc_o[2][8][4];
    #pragma unroll
    for (int mf = 0; mf < 2; mf++)
        #pragma unroll
        for (int nf = 0; nf < 8; nf++)
            #pragma unroll
            for (int e = 0; e < 4; e++) acc_o[mf][nf][e] = 0.f;
    float psum[2][2] = {{0.f, 0.f}, {0.f, 0.f}};

    // =================== pass 1: rowsums + unnormalized O ==================
    for (int kt = 0; kt < 16; ++kt) {
        const int kb = kt*128;
        float4 kv4[8], vv4[8];
        #pragma unroll
        for (int i = 0; i < 8; i++) {
            const int f = i*256 + tid;
            kv4[i] = *(const float4*)(Kb + (size_t)(kb + (f >> 4))*DH + (f & 15)*4);
            vv4[i] = *(const float4*)(Vb + (size_t)(kb + (f >> 4))*DH + (f & 15)*4);
        }
        __syncthreads();
        #pragma unroll
        for (int i = 0; i < 8; i++) {
            const int f = i*256 + tid;
            const int boff = (f >> 4)*144 + (f & 15)*8;
            uint2 uh, ul;
            split_pack_h(kv4[i], uh, ul);
            *(uint2*)(sm + AF_KH + boff) = uh;
            *(uint2*)(sm + AF_KL + boff) = ul;
            split_pack_h(vv4[i], uh, ul);
            *(uint2*)(sm + AF_VH + boff) = uh;
            *(uint2*)(sm + AF_VL + boff) = ul;
        }
        __syncthreads();

        // S = Q K^T  (2-product fp16)
        float acc_s[2][8][4];
        #pragma unroll
        for (int mf = 0; mf < 2; mf++)
            #pragma unroll
            for (int nf = 0; nf < 8; nf++)
                #pragma unroll
                for (int e = 0; e < 4; e++) acc_s[mf][nf][e] = 0.f;
        #pragma unroll
        for (int ks = 0; ks < 4; ks++) {
            uint32_t ah[2][4];
            #pragma unroll
            for (int mf = 0; mf < 2; mf++)
                ldsm4(ah[mf], smb + AF_QH + (mw + mf*16 + l15)*144 + (ks*16 + lq*8)*2);
            #pragma unroll
            for (int nf = 0; nf < 8; nf++) {
                const uint32_t bo = (nw + nf*8 + l7)*144 + (ks*16 + lh*8)*2;
                uint32_t bhf[2], blf[2];
                ldsm2(bhf, smb + AF_KH + bo);
                ldsm2(blf, smb + AF_KL + bo);
                #pragma unroll
                for (int mf = 0; mf < 2; mf++) {
                    mma16816(acc_s[mf][nf], ah[mf], bhf);
                    mma16816(acc_s[mf][nf], ah[mf], blf);
                }
            }
        }

        // exp + rowsum + hi-only E fragments (registers)
        uint32_t eh[2][8][2];
        #pragma unroll
        for (int nf = 0; nf < 8; nf++) {
            const int c = nw + nf*8 + cq;
            const float dec0 = __expf((float)(kb + c)     * -0.02f);
            const float dec1 = __expf((float)(kb + c + 1) * -0.02f);
            #pragma unroll
            for (int mf = 0; mf < 2; mf++) {
                const float e0 = __expf(fmaf(acc_s[mf][nf][0], 0.125f, dec0));
                const float e1 = __expf(fmaf(acc_s[mf][nf][1], 0.125f, dec1));
                const float e2 = __expf(fmaf(acc_s[mf][nf][2], 0.125f, dec0));
                const float e3 = __expf(fmaf(acc_s[mf][nf][3], 0.125f, dec1));
                psum[mf][0] += e0 + e1;
                psum[mf][1] += e2 + e3;
                eh[mf][nf][0] = pack2hi(e0, e1);
                eh[mf][nf][1] = pack2hi(e2, e3);
            }
        }

        // PV: O += E @ V  (E hi-only A fragments, V hi+lo)
        #pragma unroll
        for (int ks2 = 0; ks2 < 4; ks2++) {
            uint32_t pah[2][4];
            #pragma unroll
            for (int mf = 0; mf < 2; mf++) {
                pah[mf][0] = eh[mf][2*ks2][0];
                pah[mf][1] = eh[mf][2*ks2][1];
                pah[mf][2] = eh[mf][2*ks2+1][0];
                pah[mf][3] = eh[mf][2*ks2+1][1];
            }
            #pragma unroll
            for (int nf = 0; nf < 8; nf++) {
                const uint32_t bo = (nw + ks2*16 + l15)*144 + (nf*8)*2;
                uint32_t bhf[2], blf[2];
                ldsm2t(bhf, smb + AF_VH + bo);
                ldsm2t(blf, smb + AF_VL + bo);
                #pragma unroll
                for (int mf = 0; mf < 2; mf++) {
                    mma16816(acc_o[mf][nf], pah[mf], bhf);
                    mma16816(acc_o[mf][nf], pah[mf], blf);
                }
            }
        }
    }

    // ---- rowsums -> invs ----
    #pragma unroll
    for (int off = 1; off < 4; off <<= 1) {
        psum[0][0] += __shfl_xor_sync(0xffffffffu, psum[0][0], off);
        psum[0][1] += __shfl_xor_sync(0xffffffffu, psum[0][1], off);
        psum[1][0] += __shfl_xor_sync(0xffffffffu, psum[1][0], off);
        psum[1][1] += __shfl_xor_sync(0xffffffffu, psum[1][1], off);
    }
    __syncthreads();
    float* ps   = (float*)(sm + AF_PS);
    float* invs = (float*)(sm + AF_INV);
    if ((lane & 3) == 0) {
        #pragma unroll
        for (int mf = 0; mf < 2; mf++)
            #pragma unroll
            for (int h = 0; h < 2; h++)
                ps[wid*32 + mf*16 + h*8 + g] = psum[mf][h];
    }
    __syncthreads();
    if (tid < 128) invs[tid] = 1.0f / (ps[tid] + ps[tid + 128]);
    __syncthreads();

    // ---- scale O, reduce warp pairs via smem, write g_O ----
    #pragma unroll
    for (int mf = 0; mf < 2; mf++) {
        const float inv0 = invs[mw + mf*16 + g];
        const float inv1 = invs[mw + mf*16 + 8 + g];
        #pragma unroll
        for (int nf = 0; nf < 8; nf++) {
            acc_o[mf][nf][0] *= inv0; acc_o[mf][nf][1] *= inv0;
            acc_o[mf][nf][2] *= inv1; acc_o[mf][nf][3] *= inv1;
        }
    }
    float* exch = (float*)(sm + AF_KH);  // 32KB scratch (K/V stage dead)
    if (wid >= 4) {
        #pragma unroll
        for (int mf = 0; mf < 2; mf++)
            #pragma unroll
            for (int nf = 0; nf < 8; nf++) {
                float* e0 = exch + (wid & 3)*2048 + (mf*16 + g)*64 + nf*8 + cq;
                *(float2*)(e0)       = make_float2(acc_o[mf][nf][0], acc_o[mf][nf][1]);
                *(float2*)(e0 + 512) = make_float2(acc_o[mf][nf][2], acc_o[mf][nf][3]);
            }
    }
    __syncthreads();
    if (wid < 4) {
        const int b = bh >> 3, h = bh & 7;
        #pragma unroll
        for (int mf = 0; mf < 2; mf++) {
            const int r0 = q0 + mw + mf*16 + g;
            #pragma unroll
            for (int nf = 0; nf < 8; nf++) {
                const float* e0 = exch + wid*2048 + (mf*16 + g)*64 + nf*8 + cq;
                const float2 p0 = *(const float2*)(e0);
                const float2 p1 = *(const float2*)(e0 + 512);
                float* op = g_O + (size_t)(b*NSEQ + r0)*DMODEL + h*DH + nf*8 + cq;
                *(float2*)(op)            = make_float2(acc_o[mf][nf][0] + p0.x,
                                                        acc_o[mf][nf][1] + p0.y);
                *(float2*)(op + 8*DMODEL) = make_float2(acc_o[mf][nf][2] + p1.x,
                                                        acc_o[mf][nf][3] + p1.y);
            }
        }
    }
    __syncthreads();

    // =================== pass 2: recompute E, write attn ===================
    for (int kt = 0; kt < 16; ++kt) {
        const int kb = kt*128;
        float4 kv4[8];
        #pragma unroll
        for (int i = 0; i < 8; i++) {
            const int f = i*256 + tid;
            kv4[i] = *(const float4*)(Kb + (size_t)(kb + (f >> 4))*DH + (f & 15)*4);
        }
        __syncthreads();
        #pragma unroll
        for (int i = 0; i < 8; i++) {
            const int f = i*256 + tid;
            const int boff = (f >> 4)*144 + (f & 15)*8;
            uint2 uh, ul;
            split_pack_h(kv4[i], uh, ul);
            *(uint2*)(sm + AF_KH + boff) = uh;
            *(uint2*)(sm + AF_KL + boff) = ul;
        }
        __syncthreads();

        float acc_s[2][8][4];
        #pragma unroll
        for (int mf = 0; mf < 2; mf++)
            #pragma unroll
            for (int nf = 0; nf < 8; nf++)
                #pragma unroll
                for (int e = 0; e < 4; e++) acc_s[mf][nf][e] = 0.f;
        #pragma unroll
        for (int ks = 0; ks < 4; ks++) {
            uint32_t ah[2][4];
            #pragma unroll
            for (int mf = 0; mf < 2; mf++)
                ldsm4(ah[mf], smb + AF_QH + (mw + mf*16 + l15)*144 + (ks*16 + lq*8)*2);
            #pragma unroll
            for (int nf = 0; nf < 8; nf++) {
                const uint32_t bo = (nw + nf*8 + l7)*144 + (ks*16 + lh*8)*2;
                uint32_t bhf[2], blf[2];
                ldsm2(bhf, smb + AF_KH + bo);
                ldsm2(blf, smb + AF_KL + bo);
                #pragma unroll
                for (int mf = 0; mf < 2; mf++) {
                    mma16816(acc_s[mf][nf], ah[mf], bhf);
                    mma16816(acc_s[mf][nf], ah[mf], blf);
                }
            }
        }

        #pragma unroll
        for (int mf = 0; mf < 2; mf++) {
            const float inv0 = invs[mw + mf*16 + g];
            const float inv1 = invs[mw + mf*16 + 8 + g];
            const int r0 = q0 + mw + mf*16 + g;
            #pragma unroll
            for (int nf = 0; nf < 8; nf++) {
                const int c = nw + nf*8 + cq;
                const float dec0 = __expf((float)(kb + c)     * -0.02f);
                const float dec1 = __expf((float)(kb + c + 1) * -0.02f);
                const float e0 = __expf(fmaf(acc_s[mf][nf][0], 0.125f, dec0)) * inv0;
                const float e1 = __expf(fmaf(acc_s[mf][nf][1], 0.125f, dec1)) * inv0;
                const float e2 = __expf(fmaf(acc_s[mf][nf][2], 0.125f, dec0)) * inv1;
                const float e3 = __expf(fmaf(acc_s[mf][nf][3], 0.125f, dec1)) * inv1;
                float* p = attn + ((size_t)bh*NSEQ + r0)*NSEQ + kb + c;
                *(float2*)(p)          = make_float2(e0, e1);
                *(float2*)(p + 8*NSEQ) = make_float2(e2, e3);
            }
        }
    }
}

// ---------------- LayerNorm (unchanged) -----------------------------------
__global__ void __launch_bounds__(256)
ln_kernel(const float* __restrict__ gamma, const float* __restrict__ beta,
          float* __restrict__ out)
{
    const int r = blockIdx.x, tid = threadIdx.x;
    const float* y = g_Y + (size_t)r*DMODEL;
    const float a = y[tid], b = y[tid + 256];
    float s  = a + b;
    float sq = a*a + b*b;
    #pragma unroll
    for (int off = 16; off; off >>= 1) {
        s  += __shfl_xor_sync(0xffffffffu, s,  off);
        sq += __shfl_xor_sync(0xffffffffu, sq, off);
    }
    __shared__ float ws[8], wq[8];
    __shared__ float mean_s, inv_s;
    if ((tid & 31) == 0) { ws[tid >> 5] = s; wq[tid >> 5] = sq; }
    __syncthreads();
    if (tid == 0) {
        float S = 0.f, Q = 0.f;
        #pragma unroll
        for (int i = 0; i < 8; i++) { S += ws[i]; Q += wq[i]; }
        const float mean = S * (1.0f/512.0f);
        const float var  = Q * (1.0f/512.0f) - mean*mean;
        mean_s = mean;
        inv_s  = rsqrtf(var + 1e-5f);
    }
    __syncthreads();
    out[(size_t)r*DMODEL + tid]       = (a - mean_s)*inv_s*gamma[tid]       + beta[tid];
    out[(size_t)r*DMODEL + tid + 256] = (b - mean_s)*inv_s*gamma[tid + 256] + beta[tid + 256];
}

// ---------------- launch ---------------------------------------------------
extern "C" void kernel_launch(void* const* d_in, const int* in_sizes, int n_in,
                              void* d_out, int out_size)
{
    const float* x        = (const float*)d_in[0];
    const float* w_qkv    = (const float*)d_in[1];
    const float* w_unify  = (const float*)d_in[2];
    const float* b_unify  = (const float*)d_in[3];
    const float* ln_gamma = (const float*)d_in[4];
    const float* ln_beta  = (const float*)d_in[5];

    float* out_ln   = (float*)d_out;
    float* out_attn = out_ln + (size_t)ROWS*DMODEL;

    cudaFuncSetAttribute(gemm_hmma<0>, cudaFuncAttributeMaxDynamicSharedMemorySize, GM_SMEM);
    cudaFuncSetAttribute(gemm_hmma<1>, cudaFuncAttributeMaxDynamicSharedMemorySize, GM_SMEM);
    cudaFuncSetAttribute(attn_fused,   cudaFuncAttributeMaxDynamicSharedMemorySize, AF_SMEM);

    // 1) QKV projection into [bh][n][dh]
    gemm_hmma<0><<<dim3(12, 64), 256, GM_SMEM>>>(x, w_qkv, nullptr, 3*DMODEL);
    // 2) fused attention: O + normalized attn write
    attn_fused<<<dim3(16, 32), 256, AF_SMEM>>>(out_attn);
    // 3) unify GEMM + bias
    gemm_hmma<1><<<dim3(4, 64), 256, GM_SMEM>>>(nullptr, w_unify, b_unify, DMODEL);
    // 4) LayerNorm -> first output
    ln_kernel<<<ROWS, 256>>>(ln_gamma, ln_beta, out_ln);
}